// round 2
// baseline (speedup 1.0000x reference)
#include <cuda_runtime.h>
#include <cuda_bf16.h>

#define B_USERS 2048
#define P_POSTS 16384
#define LEN     50
#define D_EMB   300
#define NFILT   100
#define HID     64
#define INF_    768

// ---------------- scratch (device globals; no allocation) ----------------
__device__ int   g_segstart[B_USERS + 1];
__device__ float g_hist[(size_t)B_USERS * LEN * D_EMB];   // [B, L, D]  ~123 MB
__device__ float g_rec[B_USERS * HID];

// ---------------- kernel A: segment offsets via binary search ----------------
__global__ void seg_bounds_kernel(const int* __restrict__ seg_ids) {
    int b = blockIdx.x * blockDim.x + threadIdx.x;
    if (b > B_USERS) return;
    int lo = 0, hi = P_POSTS;
    while (lo < hi) {
        int mid = (lo + hi) >> 1;
        if (seg_ids[mid] < b) lo = mid + 1; else hi = mid;
    }
    g_segstart[b] = lo;
}

// ---------------- kernel B: segment-mean of embeddings -> g_hist ----------------
// grid = (LEN, B_USERS), block = 128 threads.  Each block handles one (b, l).
__global__ void hist_kernel(const int* __restrict__ tokens,
                            const float* __restrict__ emb) {
    int l = blockIdx.x;
    int b = blockIdx.y;
    int tid = threadIdx.x;
    int s = g_segstart[b], e = g_segstart[b + 1];

    float a0 = 0.f, a1 = 0.f, a2 = 0.f;
    for (int p = s; p < e; ++p) {
        int tok = __ldg(tokens + p * LEN + l);          // warp-uniform load
        const float* row = emb + (size_t)tok * D_EMB;
        a0 += __ldg(row + tid);
        a1 += __ldg(row + tid + 128);
        if (tid < 44) a2 += __ldg(row + tid + 256);
    }
    float scale = 1.0f / (float)max(e - s, 1);
    float* o = g_hist + ((size_t)b * LEN + l) * D_EMB;
    o[tid]        = a0 * scale;
    o[tid + 128]  = a1 * scale;
    if (tid < 44) o[tid + 256] = a2 * scale;
}

// ---------------- kernel C: TextCNN conv + relu + maxpool + rec GEMM ----------------
// One feature (nf of a K-group) per thread.  Rolling register window over rows:
// each warp-uniform LDS feeds K FMAs -> FMA-pipe bound, not LDS bound.
template <int K>
__device__ __forceinline__ float conv_feature(const float* __restrict__ sh,
                                              const float* __restrict__ w,
                                              float bias) {
    constexpr int T = LEN - K + 1;
    float acc[T];
#pragma unroll
    for (int t = 0; t < T; ++t) acc[t] = 0.f;

    for (int d = 0; d < D_EMB; ++d) {
        float wr[K];
#pragma unroll
        for (int k = 0; k < K; ++k) wr[k] = __ldg(w + d * K + k);
        float hw[K];
#pragma unroll
        for (int k = 0; k < K - 1; ++k) hw[k + 1] = sh[k * D_EMB + d];
#pragma unroll
        for (int t = 0; t < T; ++t) {
#pragma unroll
            for (int k = 0; k < K - 1; ++k) hw[k] = hw[k + 1];
            hw[K - 1] = sh[(t + K - 1) * D_EMB + d];     // broadcast LDS
#pragma unroll
            for (int k = 0; k < K; ++k) acc[t] = fmaf(hw[k], wr[k], acc[t]);
        }
    }
    float m = acc[0];
#pragma unroll
    for (int t = 1; t < T; ++t) m = fmaxf(m, acc[t]);
    return fmaxf(m + bias, 0.f);                          // relu(max+b) == max relu
}

__global__ void __launch_bounds__(384)
conv_kernel(const float* __restrict__ w3, const float* __restrict__ b3,
            const float* __restrict__ w4, const float* __restrict__ b4,
            const float* __restrict__ w5, const float* __restrict__ b5,
            const float* __restrict__ hw_, const float* __restrict__ hb_) {
    extern __shared__ float sh[];                 // [LEN*D_EMB hist][3*NFILT feats]
    float* shf = sh + LEN * D_EMB;
    int b = blockIdx.x;

    const float* hsrc = g_hist + (size_t)b * (LEN * D_EMB);
    for (int i = threadIdx.x; i < LEN * D_EMB; i += 384) sh[i] = hsrc[i];
    __syncthreads();

    int g  = threadIdx.x >> 7;        // K-group (0:K=3, 1:K=4, 2:K=5) -> warp-uniform
    int nf = threadIdx.x & 127;
    if (nf < NFILT) {
        float f;
        if (g == 0)      f = conv_feature<3>(sh, w3 + nf * D_EMB * 3, __ldg(b3 + nf));
        else if (g == 1) f = conv_feature<4>(sh, w4 + nf * D_EMB * 4, __ldg(b4 + nf));
        else             f = conv_feature<5>(sh, w5 + nf * D_EMB * 5, __ldg(b5 + nf));
        shf[g * NFILT + nf] = f;
    }
    __syncthreads();

    if (threadIdx.x < HID) {
        int o = threadIdx.x;
        const float* wr = hw_ + o * (3 * NFILT);
        float r = __ldg(hb_ + o);
#pragma unroll 4
        for (int j = 0; j < 3 * NFILT; ++j) r = fmaf(shf[j], __ldg(wr + j), r);
        g_rec[b * HID + o] = r;
    }
}

// ---------------- kernel D: fc_out on root features + final add ----------------
__global__ void __launch_bounds__(128)
fc_kernel(const float* __restrict__ x, const int* __restrict__ root,
          const float* __restrict__ w1, const float* __restrict__ b1,
          const float* __restrict__ w2, const float* __restrict__ b2,
          float* __restrict__ out) {
    __shared__ float sx[INF_];
    __shared__ float shh[2 * HID];
    int b = blockIdx.x;
    const float* xr = x + (size_t)__ldg(root + b) * INF_;
    for (int i = threadIdx.x; i < INF_; i += 128) sx[i] = __ldg(xr + i);
    __syncthreads();

    int o = threadIdx.x;                       // 0..127
    {
        const float* wr = w1 + o * INF_;
        float a0 = __ldg(b1 + o), a1 = 0.f, a2 = 0.f, a3 = 0.f;
        for (int d = 0; d < INF_; d += 4) {
            a0 = fmaf(sx[d],     __ldg(wr + d),     a0);
            a1 = fmaf(sx[d + 1], __ldg(wr + d + 1), a1);
            a2 = fmaf(sx[d + 2], __ldg(wr + d + 2), a2);
            a3 = fmaf(sx[d + 3], __ldg(wr + d + 3), a3);
        }
        shh[o] = fmaxf(a0 + a1 + a2 + a3, 0.f);
    }
    __syncthreads();

    if (o < HID) {
        const float* wr = w2 + o * (2 * HID);
        float a = __ldg(b2 + o);
#pragma unroll 8
        for (int j = 0; j < 2 * HID; ++j) a = fmaf(shh[j], __ldg(wr + j), a);
        out[b * HID + o] = g_rec[b * HID + o] + a;
    }
}

// ---------------- launch ----------------
extern "C" void kernel_launch(void* const* d_in, const int* in_sizes, int n_in,
                              void* d_out, int out_size) {
    const float* x        = (const float*)d_in[0];
    const int*   root     = (const int*)  d_in[1];
    const int*   tokens   = (const int*)  d_in[2];
    const int*   seg_ids  = (const int*)  d_in[3];
    const float* emb      = (const float*)d_in[4];
    const float* w3 = (const float*)d_in[5];   const float* b3 = (const float*)d_in[6];
    const float* w4 = (const float*)d_in[7];   const float* b4 = (const float*)d_in[8];
    const float* w5 = (const float*)d_in[9];   const float* b5 = (const float*)d_in[10];
    const float* hw = (const float*)d_in[11];  const float* hb = (const float*)d_in[12];
    const float* f1w = (const float*)d_in[13]; const float* f1b = (const float*)d_in[14];
    const float* f2w = (const float*)d_in[15]; const float* f2b = (const float*)d_in[16];
    float* out = (float*)d_out;

    const int conv_smem = (LEN * D_EMB + 3 * NFILT) * (int)sizeof(float);  // 61200 B
    cudaFuncSetAttribute(conv_kernel, cudaFuncAttributeMaxDynamicSharedMemorySize,
                         conv_smem);

    seg_bounds_kernel<<<(B_USERS + 1 + 255) / 256, 256>>>(seg_ids);
    {
        dim3 grid(LEN, B_USERS);
        hist_kernel<<<grid, 128>>>(tokens, emb);
    }
    conv_kernel<<<B_USERS, 384, conv_smem>>>(w3, b3, w4, b4, w5, b5, hw, hb);
    fc_kernel<<<B_USERS, 128>>>(x, root, f1w, f1b, f2w, f2b, out);
}

// round 3
// speedup vs baseline: 1.4685x; 1.4685x over previous
#include <cuda_runtime.h>
#include <cuda_bf16.h>

#define B_USERS 2048
#define P_POSTS 16384
#define LEN     50
#define D_EMB   300
#define NFILT   100
#define HID     64
#define INF_    768
#define NDP     150          // D_EMB/2 packed d-pairs

typedef unsigned long long u64;

// ---------------- scratch (device globals; no allocation) ----------------
__device__ int    g_segstart[B_USERS + 1];
__device__ float  g_hist[(size_t)B_USERS * LEN * D_EMB];   // [B, L, D]
__device__ float  g_rec[B_USERS * HID];
// packed conv weights: [(dp*K + k)*128 + nf] as float2 {w[2dp][k], w[2dp+1][k]}
__device__ float2 g_wp3[NDP * 3 * 128];
__device__ float2 g_wp4[NDP * 4 * 128];
__device__ float2 g_wp5[NDP * 5 * 128];
// transposed small GEMM weights (lane-coalesced output dim)
__device__ float  g_hwt[300 * 64];     // [j][o]
__device__ float  g_w1t[INF_ * 128];   // [d][o]
__device__ float  g_w2t[128 * 64];     // [d][j]

// ---------------- kernel A: segment offsets via binary search ----------------
__global__ void seg_bounds_kernel(const int* __restrict__ seg_ids) {
    int b = blockIdx.x * blockDim.x + threadIdx.x;
    if (b > B_USERS) return;
    int lo = 0, hi = P_POSTS;
    while (lo < hi) {
        int mid = (lo + hi) >> 1;
        if (seg_ids[mid] < b) lo = mid + 1; else hi = mid;
    }
    g_segstart[b] = lo;
}

// ---------------- prep kernel: repack/transpose all weight matrices ----------------
__global__ void prep_kernel(const float* __restrict__ w3, const float* __restrict__ w4,
                            const float* __restrict__ w5, const float* __restrict__ hw_,
                            const float* __restrict__ w1, const float* __restrict__ w2) {
    int idx = blockIdx.x * 256 + threadIdx.x;
    if (idx < 230400) {                       // conv packs (57600 + 76800 + 96000)
        const float* w; float2* dst; int K; int r = idx;
        if (r < 57600)        { w = w3; dst = g_wp3; K = 3; }
        else if (r < 134400)  { r -= 57600;  w = w4; dst = g_wp4; K = 4; }
        else                  { r -= 134400; w = w5; dst = g_wp5; K = 5; }
        int nf = r & 127; int dk = r >> 7; int dp = dk / K; int k = dk - dp * K;
        float2 v = {0.f, 0.f};
        if (nf < NFILT) {
            v.x = __ldg(w + nf * D_EMB * K + (2 * dp)     * K + k);
            v.y = __ldg(w + nf * D_EMB * K + (2 * dp + 1) * K + k);
        }
        dst[r] = v;
        return;
    }
    int i2 = idx - 230400;                    // hwt: [j][o], 300*64
    if (i2 >= 0 && i2 < 300 * 64) {
        int o = i2 & 63; int j = i2 >> 6;
        g_hwt[i2] = __ldg(hw_ + o * 300 + j);
        return;
    }
    int i3 = idx - 249600;                    // w1t: [d][o], 768*128
    if (i3 >= 0 && i3 < INF_ * 128) {
        int o = i3 & 127; int d = i3 >> 7;
        g_w1t[i3] = __ldg(w1 + o * INF_ + d);
        return;
    }
    int i4 = idx - 347904;                    // w2t: [d][j], 128*64
    if (i4 >= 0 && i4 < 128 * 64) {
        int j = i4 & 63; int d = i4 >> 6;
        g_w2t[i4] = __ldg(w2 + j * 128 + d);
    }
}

// ---------------- kernel B: segment-mean of embeddings -> g_hist ----------------
__global__ void hist_kernel(const int* __restrict__ tokens,
                            const float* __restrict__ emb) {
    int l = blockIdx.x;
    int b = blockIdx.y;
    int tid = threadIdx.x;
    int s = g_segstart[b], e = g_segstart[b + 1];

    float a0 = 0.f, a1 = 0.f, a2 = 0.f;
    float c0 = 0.f, c1 = 0.f, c2 = 0.f;
    int p = s;
    for (; p + 1 < e; p += 2) {
        int t0 = __ldg(tokens + p * LEN + l);
        int t1 = __ldg(tokens + (p + 1) * LEN + l);
        const float* r0 = emb + (size_t)t0 * D_EMB;
        const float* r1 = emb + (size_t)t1 * D_EMB;
        a0 += __ldg(r0 + tid);        c0 += __ldg(r1 + tid);
        a1 += __ldg(r0 + tid + 128);  c1 += __ldg(r1 + tid + 128);
        if (tid < 44) { a2 += __ldg(r0 + tid + 256); c2 += __ldg(r1 + tid + 256); }
    }
    if (p < e) {
        int t0 = __ldg(tokens + p * LEN + l);
        const float* r0 = emb + (size_t)t0 * D_EMB;
        a0 += __ldg(r0 + tid);
        a1 += __ldg(r0 + tid + 128);
        if (tid < 44) a2 += __ldg(r0 + tid + 256);
    }
    float scale = 1.0f / (float)max(e - s, 1);
    float* o = g_hist + ((size_t)b * LEN + l) * D_EMB;
    o[tid]       = (a0 + c0) * scale;
    o[tid + 128] = (a1 + c1) * scale;
    if (tid < 44) o[tid + 256] = (a2 + c2) * scale;
}

// ---------------- conv core: packed f32x2 rolling-window, TT positions ----------------
template <int K, int TT>
__device__ __forceinline__ float conv_half(const float2* __restrict__ sh2,
                                           const float2* __restrict__ wp,
                                           int nf, int t0) {
    u64 acc[TT];
#pragma unroll
    for (int t = 0; t < TT; ++t) acc[t] = 0ull;

    for (int dp = 0; dp < NDP; ++dp) {
        u64 wk[K];
#pragma unroll
        for (int k = 0; k < K; ++k)
            wk[k] = __ldg((const u64*)(wp + (dp * K + k) * 128 + nf));
        u64 win[K];
#pragma unroll
        for (int k = 0; k < K - 1; ++k)
            win[k] = *(const u64*)(sh2 + (t0 + k) * NDP + dp);
#pragma unroll
        for (int t = 0; t < TT; ++t) {
            win[K - 1] = *(const u64*)(sh2 + (t0 + t + K - 1) * NDP + dp);
#pragma unroll
            for (int k = 0; k < K; ++k)
                asm("fma.rn.f32x2 %0, %1, %2, %0;"
                    : "+l"(acc[t]) : "l"(win[k]), "l"(wk[k]));
#pragma unroll
            for (int k = 0; k < K - 1; ++k) win[k] = win[k + 1];
        }
    }
    float m = -1e30f;
#pragma unroll
    for (int t = 0; t < TT; ++t) {
        float lo = __uint_as_float((unsigned)(acc[t] & 0xffffffffull));
        float hi = __uint_as_float((unsigned)(acc[t] >> 32));
        m = fmaxf(m, lo + hi);
    }
    return m;
}

// ---------------- kernel C: TextCNN + maxpool + rec GEMM ----------------
// 768 threads: group g = tid>>8 (K=3/4/5), half = t-range split, nf = filter lane.
__global__ void __launch_bounds__(768, 1)
conv_kernel(const float* __restrict__ b3, const float* __restrict__ b4,
            const float* __restrict__ b5, const float* __restrict__ hb_) {
    extern __shared__ float sh[];            // [15000 hist][768 partial max][300 feats]
    float* pm  = sh + LEN * D_EMB;
    float* shf = pm + 768;
    int b = blockIdx.x;
    int tid = threadIdx.x;

    const float* hsrc = g_hist + (size_t)b * (LEN * D_EMB);
    for (int i = tid; i < LEN * D_EMB; i += 768) sh[i] = hsrc[i];
    __syncthreads();

    const float2* sh2 = (const float2*)sh;
    int g    = tid >> 8;          // warp-uniform
    int rem  = tid & 255;
    int half = rem >> 7;          // warp-uniform
    int nf   = rem & 127;

    float m;
    if (g == 0)      m = conv_half<3, 24>(sh2, g_wp3, nf, half * 24);
    else if (g == 1) m = half ? conv_half<4, 23>(sh2, g_wp4, nf, 24)
                              : conv_half<4, 24>(sh2, g_wp4, nf, 0);
    else             m = conv_half<5, 23>(sh2, g_wp5, nf, half * 23);
    pm[g * 256 + half * 128 + nf] = m;
    __syncthreads();

    if (half == 0 && nf < NFILT) {
        float mm = fmaxf(pm[g * 256 + nf], pm[g * 256 + 128 + nf]);
        const float* bp = (g == 0) ? b3 : ((g == 1) ? b4 : b5);
        shf[g * NFILT + nf] = fmaxf(mm + __ldg(bp + nf), 0.f);   // relu(max+b)
    }
    __syncthreads();

    if (tid < HID) {
        float r = __ldg(hb_ + tid);
#pragma unroll 4
        for (int j = 0; j < 3 * NFILT; ++j)
            r = fmaf(shf[j], __ldg(g_hwt + j * HID + tid), r);   // lane-coalesced
        g_rec[b * HID + tid] = r;
    }
}

// ---------------- kernel D: fc_out on root features + final add ----------------
// 8 users per block, 256 threads. Weights read lane-coalesced from g_w1t/g_w2t.
#define TB 8
__global__ void __launch_bounds__(256)
fc_kernel(const float* __restrict__ x, const int* __restrict__ root,
          const float* __restrict__ b1, const float* __restrict__ b2,
          float* __restrict__ out) {
    __shared__ float sx[TB * INF_];          // 24 KB
    __shared__ float hh[TB * 128];           // 4 KB
    __shared__ int   ridx[TB];
    int tid = threadIdx.x;
    int b0 = blockIdx.x * TB;

    if (tid < TB) ridx[tid] = __ldg(root + b0 + tid);
    __syncthreads();
    for (int i = tid; i < TB * INF_; i += 256) {
        int u = i / INF_; int d = i - u * INF_;
        sx[i] = __ldg(x + (size_t)ridx[u] * INF_ + d);
    }
    __syncthreads();

    // layer 1: h[u][o] = relu(x_u . w1[o] + b1[o]);  o = tid&127, 4 users per thread
    {
        int o  = tid & 127;
        int ug = tid >> 7;                   // 0/1 -> users [ug*4, ug*4+4)
        float acc[4] = {0.f, 0.f, 0.f, 0.f};
        for (int d = 0; d < INF_; ++d) {
            float wv = __ldg(g_w1t + d * 128 + o);   // lane-coalesced
#pragma unroll
            for (int uu = 0; uu < 4; ++uu)
                acc[uu] = fmaf(sx[(ug * 4 + uu) * INF_ + d], wv, acc[uu]);
        }
        float bb = __ldg(b1 + o);
#pragma unroll
        for (int uu = 0; uu < 4; ++uu)
            hh[(ug * 4 + uu) * 128 + o] = fmaxf(acc[uu] + bb, 0.f);
    }
    __syncthreads();

    // layer 2: out[u][j] = h_u . w2[j] + b2[j] + rec;  j = tid&63, 2 users per thread
    {
        int j = tid & 63;
        int q = tid >> 6;                    // 0..3 -> users {2q, 2q+1}
        int u0 = 2 * q, u1 = 2 * q + 1;
        float a0 = 0.f, a1 = 0.f;
        for (int d = 0; d < 128; ++d) {
            float wv = __ldg(g_w2t + d * 64 + j);    // lane-coalesced
            a0 = fmaf(hh[u0 * 128 + d], wv, a0);
            a1 = fmaf(hh[u1 * 128 + d], wv, a1);
        }
        float bb = __ldg(b2 + j);
        out[(b0 + u0) * HID + j] = a0 + bb + g_rec[(b0 + u0) * HID + j];
        out[(b0 + u1) * HID + j] = a1 + bb + g_rec[(b0 + u1) * HID + j];
    }
}

// ---------------- launch ----------------
extern "C" void kernel_launch(void* const* d_in, const int* in_sizes, int n_in,
                              void* d_out, int out_size) {
    const float* x        = (const float*)d_in[0];
    const int*   root     = (const int*)  d_in[1];
    const int*   tokens   = (const int*)  d_in[2];
    const int*   seg_ids  = (const int*)  d_in[3];
    const float* emb      = (const float*)d_in[4];
    const float* w3 = (const float*)d_in[5];   const float* b3 = (const float*)d_in[6];
    const float* w4 = (const float*)d_in[7];   const float* b4 = (const float*)d_in[8];
    const float* w5 = (const float*)d_in[9];   const float* b5 = (const float*)d_in[10];
    const float* hw = (const float*)d_in[11];  const float* hb = (const float*)d_in[12];
    const float* f1w = (const float*)d_in[13]; const float* f1b = (const float*)d_in[14];
    const float* f2w = (const float*)d_in[15]; const float* f2b = (const float*)d_in[16];
    float* out = (float*)d_out;

    const int conv_smem = (LEN * D_EMB + 768 + 3 * NFILT) * (int)sizeof(float);
    cudaFuncSetAttribute(conv_kernel, cudaFuncAttributeMaxDynamicSharedMemorySize,
                         conv_smem);

    seg_bounds_kernel<<<(B_USERS + 1 + 255) / 256, 256>>>(seg_ids);
    prep_kernel<<<(356096 + 255) / 256, 256>>>(w3, w4, w5, hw, f1w, f2w);
    {
        dim3 grid(LEN, B_USERS);
        hist_kernel<<<grid, 128>>>(tokens, emb);
    }
    conv_kernel<<<B_USERS, 768, conv_smem>>>(b3, b4, b5, hb);
    fc_kernel<<<B_USERS / TB, 256>>>(x, root, f1b, f2b, out);
}

// round 4
// speedup vs baseline: 1.9711x; 1.3422x over previous
#include <cuda_runtime.h>
#include <cuda_bf16.h>
#include <cstdint>

#define B_USERS 2048
#define P_POSTS 16384
#define LEN     50
#define D_EMB   300
#define NFILT   100
#define HID     64
#define INF_    768

#define HSTRIDE 308            // smem hist row stride (floats): conflict-free for frag loads
#define HROWS   52             // 48 positions + max kk=4 shift -> rows 0..51 (50,51 zero)
#define DC      38             // 304/8 k-chunks per kk
// frag counts per group: 38*K_g ksteps * 16 n8 tiles
#define FR0     (38*3*16)      // 1824
#define FR1     (38*4*16)      // 2432
#define FR2     (38*5*16)      // 3040
#define NFRAG   (FR0+FR1+FR2)  // 7296

// ---------------- scratch (device globals; no allocation) ----------------
__device__ int    g_segstart[B_USERS + 1];
__device__ float  g_hist[(size_t)B_USERS * LEN * D_EMB];   // [B, 50, 300]
__device__ float  g_rec[B_USERS * HID];
__device__ float  g_wfh[NFRAG * 64];   // W hi fragments, mma lane order
__device__ float  g_wfl[NFRAG * 64];   // W lo fragments
__device__ float  g_hwt[300 * 64];     // hist_w transposed [j][o]
__device__ float  g_w1t[INF_ * 128];   // fc_w1 transposed [d][o]
__device__ float  g_w2t[128 * 64];     // fc_w2 transposed [d][j]

__device__ __forceinline__ uint32_t tf32_bits(float x) {
    uint32_t r;
    asm("cvt.rna.tf32.f32 %0, %1;" : "=r"(r) : "f"(x));
    return r;
}

#define MMA_TF32(c, a, b0, b1)                                                  \
    asm("mma.sync.aligned.m16n8k8.row.col.f32.tf32.tf32.f32 "                   \
        "{%0,%1,%2,%3},{%4,%5,%6,%7},{%8,%9},{%0,%1,%2,%3};"                    \
        : "+f"(c[0]), "+f"(c[1]), "+f"(c[2]), "+f"(c[3])                         \
        : "r"(a[0]), "r"(a[1]), "r"(a[2]), "r"(a[3]), "r"(b0), "r"(b1))

// ---------------- kernel A: segment offsets via binary search ----------------
__global__ void seg_bounds_kernel(const int* __restrict__ seg_ids) {
    int b = blockIdx.x * blockDim.x + threadIdx.x;
    if (b > B_USERS) return;
    int lo = 0, hi = P_POSTS;
    while (lo < hi) {
        int mid = (lo + hi) >> 1;
        if (seg_ids[mid] < b) lo = mid + 1; else hi = mid;
    }
    g_segstart[b] = lo;
}

// ---------------- prep: weight fragments (hi/lo) + small transposes ----------------
__global__ void prep_kernel(const float* __restrict__ w3, const float* __restrict__ w4,
                            const float* __restrict__ w5, const float* __restrict__ hw_,
                            const float* __restrict__ w1, const float* __restrict__ w2) {
    int idx = blockIdx.x * 256 + threadIdx.x;
    if (idx < NFRAG * 32) {
        int lane = idx & 31;
        int frag = idx >> 5;
        int Kg; int goff; const float* w;
        if (frag < FR0)            { Kg = 3; goff = 0;        w = w3; }
        else if (frag < FR0 + FR1) { Kg = 4; goff = FR0;      w = w4; }
        else                       { Kg = 5; goff = FR0+FR1;  w = w5; }
        int rel   = frag - goff;
        int kstep = rel >> 4;
        int nb    = rel & 15;
        int kk    = kstep / DC;
        int dc    = kstep % DC;
        int gid   = lane >> 2;
        int ctid  = lane & 3;
        int f     = nb * 8 + gid;
        int d0    = dc * 8 + ctid;
        int d1    = d0 + 4;
        float v0 = 0.f, v1 = 0.f;
        if (f < NFILT) {
            if (d0 < D_EMB) v0 = __ldg(w + (f * D_EMB + d0) * Kg + kk);
            if (d1 < D_EMB) v1 = __ldg(w + (f * D_EMB + d1) * Kg + kk);
        }
        float h0 = __uint_as_float(tf32_bits(v0));
        float h1 = __uint_as_float(tf32_bits(v1));
        float l0 = __uint_as_float(tf32_bits(v0 - h0));
        float l1 = __uint_as_float(tf32_bits(v1 - h1));
        g_wfh[frag * 64 + lane * 2]     = h0;
        g_wfh[frag * 64 + lane * 2 + 1] = h1;
        g_wfl[frag * 64 + lane * 2]     = l0;
        g_wfl[frag * 64 + lane * 2 + 1] = l1;
        return;
    }
    int i2 = idx - NFRAG * 32;                 // g_hwt: 300*64
    if (i2 >= 0 && i2 < 300 * 64) {
        int o = i2 & 63; int j = i2 >> 6;
        g_hwt[i2] = __ldg(hw_ + o * 300 + j);
        return;
    }
    int i3 = i2 - 300 * 64;                    // g_w1t: 768*128
    if (i3 >= 0 && i3 < INF_ * 128) {
        int o = i3 & 127; int d = i3 >> 7;
        g_w1t[i3] = __ldg(w1 + o * INF_ + d);
        return;
    }
    int i4 = i3 - INF_ * 128;                  // g_w2t: 128*64
    if (i4 >= 0 && i4 < 128 * 64) {
        int j = i4 & 63; int d = i4 >> 6;
        g_w2t[i4] = __ldg(w2 + j * 128 + d);
    }
}

// ---------------- kernel B: segment-mean of embeddings -> g_hist ----------------
__global__ void hist_kernel(const int* __restrict__ tokens,
                            const float* __restrict__ emb) {
    int l = blockIdx.x;
    int b = blockIdx.y;
    int tid = threadIdx.x;
    int s = g_segstart[b], e = g_segstart[b + 1];

    float a0 = 0.f, a1 = 0.f, a2 = 0.f;
    float c0 = 0.f, c1 = 0.f, c2 = 0.f;
    int p = s;
    for (; p + 1 < e; p += 2) {
        int t0 = __ldg(tokens + p * LEN + l);
        int t1 = __ldg(tokens + (p + 1) * LEN + l);
        const float* r0 = emb + (size_t)t0 * D_EMB;
        const float* r1 = emb + (size_t)t1 * D_EMB;
        a0 += __ldg(r0 + tid);        c0 += __ldg(r1 + tid);
        a1 += __ldg(r0 + tid + 128);  c1 += __ldg(r1 + tid + 128);
        if (tid < 44) { a2 += __ldg(r0 + tid + 256); c2 += __ldg(r1 + tid + 256); }
    }
    if (p < e) {
        int t0 = __ldg(tokens + p * LEN + l);
        const float* r0 = emb + (size_t)t0 * D_EMB;
        a0 += __ldg(r0 + tid);
        a1 += __ldg(r0 + tid + 128);
        if (tid < 44) a2 += __ldg(r0 + tid + 256);
    }
    float scale = 1.0f / (float)max(e - s, 1);
    float* o = g_hist + ((size_t)b * LEN + l) * D_EMB;
    o[tid]       = (a0 + c0) * scale;
    o[tid + 128] = (a1 + c1) * scale;
    if (tid < 44) o[tid + 256] = (a2 + c2) * scale;
}

// ---------------- kernel C: TextCNN via tensor cores (3xTF32) ----------------
// Block = 2 users, 384 threads (12 warps). Warp job = (user, group, n8-quad).
// A = shared hist rows shifted by kk; W = pre-packed fragments from global.
__global__ void __launch_bounds__(384, 1)
conv_mma_kernel(const float* __restrict__ b3, const float* __restrict__ b4,
                const float* __restrict__ b5, const float* __restrict__ hb_) {
    extern __shared__ float sh[];             // [2][HROWS][HSTRIDE] + feats[600]
    float* feats = sh + 2 * HROWS * HSTRIDE;
    int tid  = threadIdx.x;
    int b0   = blockIdx.x * 2;

    // load 2 users' hist, zero-padded to 52 x 308
    for (int i = tid; i < 2 * HROWS * HSTRIDE; i += 384) {
        int u = i / (HROWS * HSTRIDE);
        int r = (i - u * HROWS * HSTRIDE) / HSTRIDE;
        int c = i - u * HROWS * HSTRIDE - r * HSTRIDE;
        float v = 0.f;
        if (r < LEN && c < D_EMB)
            v = g_hist[(((size_t)(b0 + u)) * LEN + r) * D_EMB + c];
        sh[i] = v;
    }
    __syncthreads();

    int warpid = tid >> 5;
    int lane   = tid & 31;
    int gid    = lane >> 2;
    int ctid   = lane & 3;

    const float2* wfh2 = (const float2*)g_wfh;
    const float2* wfl2 = (const float2*)g_wfl;

    for (int job = warpid; job < 24; job += 12) {
        int u = job / 12;
        int r = job % 12;
        int g = r >> 2;
        int q = r & 3;
        int Kg   = 3 + g;
        int goff = (g == 0) ? 0 : ((g == 1) ? FR0 : (FR0 + FR1));
        const float* shu = sh + u * (HROWS * HSTRIDE);

        float acc[3][4][4];
#pragma unroll
        for (int mt = 0; mt < 3; ++mt)
#pragma unroll
            for (int j = 0; j < 4; ++j)
#pragma unroll
                for (int c = 0; c < 4; ++c) acc[mt][j][c] = 0.f;

        for (int kk = 0; kk < Kg; ++kk) {
            const float* pa_base = shu + (gid + kk) * HSTRIDE + ctid;
            int fragrow = goff + kk * (DC * 16) + q * 4;
            for (int dc = 0; dc < DC; ++dc) {
                // W fragments (hi + lo), lane-coalesced LDG.64
                int fi = (fragrow + dc * 16) * 32 + lane;
                float2 wh[4], wl[4];
#pragma unroll
                for (int j = 0; j < 4; ++j) {
                    wh[j] = __ldg(wfh2 + fi + j * 32);
                    wl[j] = __ldg(wfl2 + fi + j * 32);
                }
                // A fragments from smem (conflict-free), split hi/lo
                uint32_t ah[3][4], al[3][4];
#pragma unroll
                for (int mt = 0; mt < 3; ++mt) {
                    const float* pa = pa_base + mt * 16 * HSTRIDE + dc * 8;
                    float x0 = pa[0];
                    float x1 = pa[8 * HSTRIDE];
                    float x2 = pa[4];
                    float x3 = pa[8 * HSTRIDE + 4];
                    ah[mt][0] = tf32_bits(x0);
                    ah[mt][1] = tf32_bits(x1);
                    ah[mt][2] = tf32_bits(x2);
                    ah[mt][3] = tf32_bits(x3);
                    al[mt][0] = tf32_bits(x0 - __uint_as_float(ah[mt][0]));
                    al[mt][1] = tf32_bits(x1 - __uint_as_float(ah[mt][1]));
                    al[mt][2] = tf32_bits(x2 - __uint_as_float(ah[mt][2]));
                    al[mt][3] = tf32_bits(x3 - __uint_as_float(ah[mt][3]));
                }
#pragma unroll
                for (int mt = 0; mt < 3; ++mt) {
#pragma unroll
                    for (int j = 0; j < 4; ++j) {
                        uint32_t bh0 = __float_as_uint(wh[j].x);
                        uint32_t bh1 = __float_as_uint(wh[j].y);
                        uint32_t bl0 = __float_as_uint(wl[j].x);
                        uint32_t bl1 = __float_as_uint(wl[j].y);
                        MMA_TF32(acc[mt][j], ah[mt], bh0, bh1);   // hi*hi
                        MMA_TF32(acc[mt][j], ah[mt], bl0, bl1);   // hi*lo
                        MMA_TF32(acc[mt][j], al[mt], bh0, bh1);   // lo*hi
                    }
                }
            }
        }

        // masked max-pool over positions, then warp-reduce over gid
        int Tg = 48 - g;                       // valid positions: 48/47/46
        const float* bp = (g == 0) ? b3 : ((g == 1) ? b4 : b5);
#pragma unroll
        for (int j = 0; j < 4; ++j) {
            float m0 = -1e30f, m1 = -1e30f;
#pragma unroll
            for (int mt = 0; mt < 3; ++mt) {
                int t_lo = mt * 16 + gid;
                int t_hi = t_lo + 8;
                if (t_lo < Tg) { m0 = fmaxf(m0, acc[mt][j][0]); m1 = fmaxf(m1, acc[mt][j][1]); }
                if (t_hi < Tg) { m0 = fmaxf(m0, acc[mt][j][2]); m1 = fmaxf(m1, acc[mt][j][3]); }
            }
#pragma unroll
            for (int off = 4; off < 32; off <<= 1) {
                m0 = fmaxf(m0, __shfl_xor_sync(0xffffffff, m0, off));
                m1 = fmaxf(m1, __shfl_xor_sync(0xffffffff, m1, off));
            }
            if (gid == 0) {
                int f0 = (q * 4 + j) * 8 + 2 * ctid;
                float* sf = feats + u * 300 + g * 100;
                if (f0 < NFILT)     sf[f0]     = fmaxf(m0 + __ldg(bp + f0), 0.f);
                if (f0 + 1 < NFILT) sf[f0 + 1] = fmaxf(m1 + __ldg(bp + f0 + 1), 0.f);
            }
        }
    }
    __syncthreads();

    // rec GEMM: [2 users] x [300 feats] x [64 outs]
    if (tid < 128) {
        int u = tid >> 6;
        int o = tid & 63;
        const float* sf = feats + u * 300;
        float r = __ldg(hb_ + o);
#pragma unroll 4
        for (int j = 0; j < 300; ++j)
            r = fmaf(sf[j], __ldg(g_hwt + j * HID + o), r);
        g_rec[(b0 + u) * HID + o] = r;
    }
}

// ---------------- kernel D: fc_out on root features + final add ----------------
#define TB 8
__global__ void __launch_bounds__(256)
fc_kernel(const float* __restrict__ x, const int* __restrict__ root,
          const float* __restrict__ b1, const float* __restrict__ b2,
          float* __restrict__ out) {
    __shared__ float sx[TB * INF_];
    __shared__ float hh[TB * 128];
    __shared__ int   ridx[TB];
    int tid = threadIdx.x;
    int b0 = blockIdx.x * TB;

    if (tid < TB) ridx[tid] = __ldg(root + b0 + tid);
    __syncthreads();
    for (int i = tid; i < TB * INF_; i += 256) {
        int u = i / INF_; int d = i - u * INF_;
        sx[i] = __ldg(x + (size_t)ridx[u] * INF_ + d);
    }
    __syncthreads();

    {
        int o  = tid & 127;
        int ug = tid >> 7;
        float acc[4] = {0.f, 0.f, 0.f, 0.f};
        for (int d = 0; d < INF_; ++d) {
            float wv = __ldg(g_w1t + d * 128 + o);
#pragma unroll
            for (int uu = 0; uu < 4; ++uu)
                acc[uu] = fmaf(sx[(ug * 4 + uu) * INF_ + d], wv, acc[uu]);
        }
        float bb = __ldg(b1 + o);
#pragma unroll
        for (int uu = 0; uu < 4; ++uu)
            hh[(ug * 4 + uu) * 128 + o] = fmaxf(acc[uu] + bb, 0.f);
    }
    __syncthreads();

    {
        int j = tid & 63;
        int q = tid >> 6;
        int u0 = 2 * q, u1 = 2 * q + 1;
        float a0 = 0.f, a1 = 0.f;
        for (int d = 0; d < 128; ++d) {
            float wv = __ldg(g_w2t + d * 64 + j);
            a0 = fmaf(hh[u0 * 128 + d], wv, a0);
            a1 = fmaf(hh[u1 * 128 + d], wv, a1);
        }
        float bb = __ldg(b2 + j);
        out[(b0 + u0) * HID + j] = a0 + bb + g_rec[(b0 + u0) * HID + j];
        out[(b0 + u1) * HID + j] = a1 + bb + g_rec[(b0 + u1) * HID + j];
    }
}

// ---------------- launch ----------------
extern "C" void kernel_launch(void* const* d_in, const int* in_sizes, int n_in,
                              void* d_out, int out_size) {
    const float* x        = (const float*)d_in[0];
    const int*   root     = (const int*)  d_in[1];
    const int*   tokens   = (const int*)  d_in[2];
    const int*   seg_ids  = (const int*)  d_in[3];
    const float* emb      = (const float*)d_in[4];
    const float* w3 = (const float*)d_in[5];   const float* b3 = (const float*)d_in[6];
    const float* w4 = (const float*)d_in[7];   const float* b4 = (const float*)d_in[8];
    const float* w5 = (const float*)d_in[9];   const float* b5 = (const float*)d_in[10];
    const float* hw = (const float*)d_in[11];  const float* hb = (const float*)d_in[12];
    const float* f1w = (const float*)d_in[13]; const float* f1b = (const float*)d_in[14];
    const float* f2w = (const float*)d_in[15]; const float* f2b = (const float*)d_in[16];
    float* out = (float*)d_out;

    const int conv_smem = (2 * HROWS * HSTRIDE + 600) * (int)sizeof(float); // ~130.5 KB
    cudaFuncSetAttribute(conv_mma_kernel, cudaFuncAttributeMaxDynamicSharedMemorySize,
                         conv_smem);

    int prep_threads = NFRAG * 32 + 300 * 64 + INF_ * 128 + 128 * 64;
    seg_bounds_kernel<<<(B_USERS + 1 + 255) / 256, 256>>>(seg_ids);
    prep_kernel<<<(prep_threads + 255) / 256, 256>>>(w3, w4, w5, hw, f1w, f2w);
    {
        dim3 grid(LEN, B_USERS);
        hist_kernel<<<grid, 128>>>(tokens, emb);
    }
    conv_mma_kernel<<<B_USERS / 2, 384, conv_smem>>>(b3, b4, b5, hb);
    fc_kernel<<<B_USERS / TB, 256>>>(x, root, f1b, f2b, out);
}

// round 5
// speedup vs baseline: 1.9797x; 1.0043x over previous
#include <cuda_runtime.h>
#include <cuda_bf16.h>
#include <cstdint>

#define B_USERS 2048
#define P_POSTS 16384
#define LEN     50
#define D_EMB   300
#define NFILT   100
#define HID     64
#define INF_    768

#define HSTRIDE 308            // smem hist row stride (floats): conflict-free for frag loads
#define HROWS   52             // 48 positions + max kk=4 shift -> rows 0..51 (50,51 zero)
#define DC      38             // 304/8 k-chunks per kk
// frag counts per group: 38*K_g ksteps * 16 n8 tiles
#define FR0     (38*3*16)      // 1824
#define FR1     (38*4*16)      // 2432
#define FR2     (38*5*16)      // 3040
#define NFRAG   (FR0+FR1+FR2)  // 7296

// ---------------- scratch (device globals; no allocation) ----------------
__device__ int    g_segstart[B_USERS + 1];
__device__ float  g_hist[(size_t)B_USERS * LEN * D_EMB];   // [B, 50, 300]
__device__ float  g_rec[B_USERS * HID];
__device__ float  g_wfh[NFRAG * 64];   // W hi fragments, mma lane order
__device__ float  g_wfl[NFRAG * 64];   // W lo fragments
__device__ float  g_hwt[300 * 64];     // hist_w transposed [j][o]
__device__ float  g_w1t[INF_ * 128];   // fc_w1 transposed [d][o]
__device__ float  g_w2t[128 * 64];     // fc_w2 transposed [d][j]

__device__ __forceinline__ uint32_t tf32_bits(float x) {
    uint32_t r;
    asm("cvt.rna.tf32.f32 %0, %1;" : "=r"(r) : "f"(x));
    return r;
}

#define MMA_TF32(c, a, b0, b1)                                                  \
    asm("mma.sync.aligned.m16n8k8.row.col.f32.tf32.tf32.f32 "                   \
        "{%0,%1,%2,%3},{%4,%5,%6,%7},{%8,%9},{%0,%1,%2,%3};"                    \
        : "+f"(c[0]), "+f"(c[1]), "+f"(c[2]), "+f"(c[3])                         \
        : "r"(a[0]), "r"(a[1]), "r"(a[2]), "r"(a[3]), "r"(b0), "r"(b1))

// ---------------- kernel A: segment offsets via binary search ----------------
__global__ void seg_bounds_kernel(const int* __restrict__ seg_ids) {
    int b = blockIdx.x * blockDim.x + threadIdx.x;
    if (b > B_USERS) return;
    int lo = 0, hi = P_POSTS;
    while (lo < hi) {
        int mid = (lo + hi) >> 1;
        if (seg_ids[mid] < b) lo = mid + 1; else hi = mid;
    }
    g_segstart[b] = lo;
}

// ---------------- prep: weight fragments (hi/lo) + small transposes ----------------
__global__ void prep_kernel(const float* __restrict__ w3, const float* __restrict__ w4,
                            const float* __restrict__ w5, const float* __restrict__ hw_,
                            const float* __restrict__ w1, const float* __restrict__ w2) {
    int idx = blockIdx.x * 256 + threadIdx.x;
    if (idx < NFRAG * 32) {
        int lane = idx & 31;
        int frag = idx >> 5;
        int Kg; int goff; const float* w;
        if (frag < FR0)            { Kg = 3; goff = 0;        w = w3; }
        else if (frag < FR0 + FR1) { Kg = 4; goff = FR0;      w = w4; }
        else                       { Kg = 5; goff = FR0+FR1;  w = w5; }
        int rel   = frag - goff;
        int kstep = rel >> 4;
        int nb    = rel & 15;
        int kk    = kstep / DC;
        int dc    = kstep % DC;
        int gid   = lane >> 2;
        int ctid  = lane & 3;
        int f     = nb * 8 + gid;
        int d0    = dc * 8 + ctid;
        int d1    = d0 + 4;
        float v0 = 0.f, v1 = 0.f;
        if (f < NFILT) {
            if (d0 < D_EMB) v0 = __ldg(w + (f * D_EMB + d0) * Kg + kk);
            if (d1 < D_EMB) v1 = __ldg(w + (f * D_EMB + d1) * Kg + kk);
        }
        float h0 = __uint_as_float(tf32_bits(v0));
        float h1 = __uint_as_float(tf32_bits(v1));
        float l0 = __uint_as_float(tf32_bits(v0 - h0));
        float l1 = __uint_as_float(tf32_bits(v1 - h1));
        g_wfh[frag * 64 + lane * 2]     = h0;
        g_wfh[frag * 64 + lane * 2 + 1] = h1;
        g_wfl[frag * 64 + lane * 2]     = l0;
        g_wfl[frag * 64 + lane * 2 + 1] = l1;
        return;
    }
    int i2 = idx - NFRAG * 32;                 // g_hwt: 300*64
    if (i2 >= 0 && i2 < 300 * 64) {
        int o = i2 & 63; int j = i2 >> 6;
        g_hwt[i2] = __ldg(hw_ + o * 300 + j);
        return;
    }
    int i3 = i2 - 300 * 64;                    // g_w1t: 768*128
    if (i3 >= 0 && i3 < INF_ * 128) {
        int o = i3 & 127; int d = i3 >> 7;
        g_w1t[i3] = __ldg(w1 + o * INF_ + d);
        return;
    }
    int i4 = i3 - INF_ * 128;                  // g_w2t: 128*64
    if (i4 >= 0 && i4 < 128 * 64) {
        int j = i4 & 63; int d = i4 >> 6;
        g_w2t[i4] = __ldg(w2 + j * 128 + d);
    }
}

// ---------------- kernel B: segment-mean of embeddings -> g_hist ----------------
__global__ void hist_kernel(const int* __restrict__ tokens,
                            const float* __restrict__ emb) {
    int l = blockIdx.x;
    int b = blockIdx.y;
    int tid = threadIdx.x;
    int s = g_segstart[b], e = g_segstart[b + 1];

    float a0 = 0.f, a1 = 0.f, a2 = 0.f;
    float c0 = 0.f, c1 = 0.f, c2 = 0.f;
    int p = s;
    for (; p + 1 < e; p += 2) {
        int t0 = __ldg(tokens + p * LEN + l);
        int t1 = __ldg(tokens + (p + 1) * LEN + l);
        const float* r0 = emb + (size_t)t0 * D_EMB;
        const float* r1 = emb + (size_t)t1 * D_EMB;
        a0 += __ldg(r0 + tid);        c0 += __ldg(r1 + tid);
        a1 += __ldg(r0 + tid + 128);  c1 += __ldg(r1 + tid + 128);
        if (tid < 44) { a2 += __ldg(r0 + tid + 256); c2 += __ldg(r1 + tid + 256); }
    }
    if (p < e) {
        int t0 = __ldg(tokens + p * LEN + l);
        const float* r0 = emb + (size_t)t0 * D_EMB;
        a0 += __ldg(r0 + tid);
        a1 += __ldg(r0 + tid + 128);
        if (tid < 44) a2 += __ldg(r0 + tid + 256);
    }
    float scale = 1.0f / (float)max(e - s, 1);
    float* o = g_hist + ((size_t)b * LEN + l) * D_EMB;
    o[tid]       = (a0 + c0) * scale;
    o[tid + 128] = (a1 + c1) * scale;
    if (tid < 44) o[tid + 256] = (a2 + c2) * scale;
}

// ---------------- kernel C: TextCNN via tensor cores (3xTF32) ----------------
// Block = 2 users, 384 threads (12 warps). Warp job = (user, group, n8-quad).
// A = shared hist rows shifted by kk; W = pre-packed fragments from global.
__global__ void __launch_bounds__(384, 1)
conv_mma_kernel(const float* __restrict__ b3, const float* __restrict__ b4,
                const float* __restrict__ b5, const float* __restrict__ hb_) {
    extern __shared__ float sh[];             // [2][HROWS][HSTRIDE] + feats[600]
    float* feats = sh + 2 * HROWS * HSTRIDE;
    int tid  = threadIdx.x;
    int b0   = blockIdx.x * 2;

    // load 2 users' hist, zero-padded to 52 x 308
    for (int i = tid; i < 2 * HROWS * HSTRIDE; i += 384) {
        int u = i / (HROWS * HSTRIDE);
        int r = (i - u * HROWS * HSTRIDE) / HSTRIDE;
        int c = i - u * HROWS * HSTRIDE - r * HSTRIDE;
        float v = 0.f;
        if (r < LEN && c < D_EMB)
            v = g_hist[(((size_t)(b0 + u)) * LEN + r) * D_EMB + c];
        sh[i] = v;
    }
    __syncthreads();

    int warpid = tid >> 5;
    int lane   = tid & 31;
    int gid    = lane >> 2;
    int ctid   = lane & 3;

    const float2* wfh2 = (const float2*)g_wfh;
    const float2* wfl2 = (const float2*)g_wfl;

    for (int job = warpid; job < 24; job += 12) {
        int u = job / 12;
        int r = job % 12;
        int g = r >> 2;
        int q = r & 3;
        int Kg   = 3 + g;
        int goff = (g == 0) ? 0 : ((g == 1) ? FR0 : (FR0 + FR1));
        const float* shu = sh + u * (HROWS * HSTRIDE);

        float acc[3][4][4];
#pragma unroll
        for (int mt = 0; mt < 3; ++mt)
#pragma unroll
            for (int j = 0; j < 4; ++j)
#pragma unroll
                for (int c = 0; c < 4; ++c) acc[mt][j][c] = 0.f;

        for (int kk = 0; kk < Kg; ++kk) {
            const float* pa_base = shu + (gid + kk) * HSTRIDE + ctid;
            int fragrow = goff + kk * (DC * 16) + q * 4;
            for (int dc = 0; dc < DC; ++dc) {
                // W fragments (hi + lo), lane-coalesced LDG.64
                int fi = (fragrow + dc * 16) * 32 + lane;
                float2 wh[4], wl[4];
#pragma unroll
                for (int j = 0; j < 4; ++j) {
                    wh[j] = __ldg(wfh2 + fi + j * 32);
                    wl[j] = __ldg(wfl2 + fi + j * 32);
                }
                // A fragments from smem (conflict-free), split hi/lo
                uint32_t ah[3][4], al[3][4];
#pragma unroll
                for (int mt = 0; mt < 3; ++mt) {
                    const float* pa = pa_base + mt * 16 * HSTRIDE + dc * 8;
                    float x0 = pa[0];
                    float x1 = pa[8 * HSTRIDE];
                    float x2 = pa[4];
                    float x3 = pa[8 * HSTRIDE + 4];
                    ah[mt][0] = tf32_bits(x0);
                    ah[mt][1] = tf32_bits(x1);
                    ah[mt][2] = tf32_bits(x2);
                    ah[mt][3] = tf32_bits(x3);
                    al[mt][0] = tf32_bits(x0 - __uint_as_float(ah[mt][0]));
                    al[mt][1] = tf32_bits(x1 - __uint_as_float(ah[mt][1]));
                    al[mt][2] = tf32_bits(x2 - __uint_as_float(ah[mt][2]));
                    al[mt][3] = tf32_bits(x3 - __uint_as_float(ah[mt][3]));
                }
#pragma unroll
                for (int mt = 0; mt < 3; ++mt) {
#pragma unroll
                    for (int j = 0; j < 4; ++j) {
                        uint32_t bh0 = __float_as_uint(wh[j].x);
                        uint32_t bh1 = __float_as_uint(wh[j].y);
                        uint32_t bl0 = __float_as_uint(wl[j].x);
                        uint32_t bl1 = __float_as_uint(wl[j].y);
                        MMA_TF32(acc[mt][j], ah[mt], bh0, bh1);   // hi*hi
                        MMA_TF32(acc[mt][j], ah[mt], bl0, bl1);   // hi*lo
                        MMA_TF32(acc[mt][j], al[mt], bh0, bh1);   // lo*hi
                    }
                }
            }
        }

        // masked max-pool over positions, then warp-reduce over gid
        int Tg = 48 - g;                       // valid positions: 48/47/46
        const float* bp = (g == 0) ? b3 : ((g == 1) ? b4 : b5);
#pragma unroll
        for (int j = 0; j < 4; ++j) {
            float m0 = -1e30f, m1 = -1e30f;
#pragma unroll
            for (int mt = 0; mt < 3; ++mt) {
                int t_lo = mt * 16 + gid;
                int t_hi = t_lo + 8;
                if (t_lo < Tg) { m0 = fmaxf(m0, acc[mt][j][0]); m1 = fmaxf(m1, acc[mt][j][1]); }
                if (t_hi < Tg) { m0 = fmaxf(m0, acc[mt][j][2]); m1 = fmaxf(m1, acc[mt][j][3]); }
            }
#pragma unroll
            for (int off = 4; off < 32; off <<= 1) {
                m0 = fmaxf(m0, __shfl_xor_sync(0xffffffff, m0, off));
                m1 = fmaxf(m1, __shfl_xor_sync(0xffffffff, m1, off));
            }
            if (gid == 0) {
                int f0 = (q * 4 + j) * 8 + 2 * ctid;
                float* sf = feats + u * 300 + g * 100;
                if (f0 < NFILT)     sf[f0]     = fmaxf(m0 + __ldg(bp + f0), 0.f);
                if (f0 + 1 < NFILT) sf[f0 + 1] = fmaxf(m1 + __ldg(bp + f0 + 1), 0.f);
            }
        }
    }
    __syncthreads();

    // rec GEMM: [2 users] x [300 feats] x [64 outs]
    if (tid < 128) {
        int u = tid >> 6;
        int o = tid & 63;
        const float* sf = feats + u * 300;
        float r = __ldg(hb_ + o);
#pragma unroll 4
        for (int j = 0; j < 300; ++j)
            r = fmaf(sf[j], __ldg(g_hwt + j * HID + o), r);
        g_rec[(b0 + u) * HID + o] = r;
    }
}

// ---------------- kernel D: fc_out on root features + final add ----------------
#define TB 8
__global__ void __launch_bounds__(256)
fc_kernel(const float* __restrict__ x, const int* __restrict__ root,
          const float* __restrict__ b1, const float* __restrict__ b2,
          float* __restrict__ out) {
    __shared__ float sx[TB * INF_];
    __shared__ float hh[TB * 128];
    __shared__ int   ridx[TB];
    int tid = threadIdx.x;
    int b0 = blockIdx.x * TB;

    if (tid < TB) ridx[tid] = __ldg(root + b0 + tid);
    __syncthreads();
    for (int i = tid; i < TB * INF_; i += 256) {
        int u = i / INF_; int d = i - u * INF_;
        sx[i] = __ldg(x + (size_t)ridx[u] * INF_ + d);
    }
    __syncthreads();

    {
        int o  = tid & 127;
        int ug = tid >> 7;
        float acc[4] = {0.f, 0.f, 0.f, 0.f};
        for (int d = 0; d < INF_; ++d) {
            float wv = __ldg(g_w1t + d * 128 + o);
#pragma unroll
            for (int uu = 0; uu < 4; ++uu)
                acc[uu] = fmaf(sx[(ug * 4 + uu) * INF_ + d], wv, acc[uu]);
        }
        float bb = __ldg(b1 + o);
#pragma unroll
        for (int uu = 0; uu < 4; ++uu)
            hh[(ug * 4 + uu) * 128 + o] = fmaxf(acc[uu] + bb, 0.f);
    }
    __syncthreads();

    {
        int j = tid & 63;
        int q = tid >> 6;
        int u0 = 2 * q, u1 = 2 * q + 1;
        float a0 = 0.f, a1 = 0.f;
        for (int d = 0; d < 128; ++d) {
            float wv = __ldg(g_w2t + d * 64 + j);
            a0 = fmaf(hh[u0 * 128 + d], wv, a0);
            a1 = fmaf(hh[u1 * 128 + d], wv, a1);
        }
        float bb = __ldg(b2 + j);
        out[(b0 + u0) * HID + j] = a0 + bb + g_rec[(b0 + u0) * HID + j];
        out[(b0 + u1) * HID + j] = a1 + bb + g_rec[(b0 + u1) * HID + j];
    }
}

// ---------------- launch ----------------
extern "C" void kernel_launch(void* const* d_in, const int* in_sizes, int n_in,
                              void* d_out, int out_size) {
    const float* x        = (const float*)d_in[0];
    const int*   root     = (const int*)  d_in[1];
    const int*   tokens   = (const int*)  d_in[2];
    const int*   seg_ids  = (const int*)  d_in[3];
    const float* emb      = (const float*)d_in[4];
    const float* w3 = (const float*)d_in[5];   const float* b3 = (const float*)d_in[6];
    const float* w4 = (const float*)d_in[7];   const float* b4 = (const float*)d_in[8];
    const float* w5 = (const float*)d_in[9];   const float* b5 = (const float*)d_in[10];
    const float* hw = (const float*)d_in[11];  const float* hb = (const float*)d_in[12];
    const float* f1w = (const float*)d_in[13]; const float* f1b = (const float*)d_in[14];
    const float* f2w = (const float*)d_in[15]; const float* f2b = (const float*)d_in[16];
    float* out = (float*)d_out;

    const int conv_smem = (2 * HROWS * HSTRIDE + 600) * (int)sizeof(float); // ~130.5 KB
    cudaFuncSetAttribute(conv_mma_kernel, cudaFuncAttributeMaxDynamicSharedMemorySize,
                         conv_smem);

    int prep_threads = NFRAG * 32 + 300 * 64 + INF_ * 128 + 128 * 64;
    seg_bounds_kernel<<<(B_USERS + 1 + 255) / 256, 256>>>(seg_ids);
    prep_kernel<<<(prep_threads + 255) / 256, 256>>>(w3, w4, w5, hw, f1w, f2w);
    {
        dim3 grid(LEN, B_USERS);
        hist_kernel<<<grid, 128>>>(tokens, emb);
    }
    conv_mma_kernel<<<B_USERS / 2, 384, conv_smem>>>(b3, b4, b5, hb);
    fc_kernel<<<B_USERS / TB, 256>>>(x, root, f1b, f2b, out);
}

// round 6
// speedup vs baseline: 3.8887x; 1.9643x over previous
#include <cuda_runtime.h>
#include <cuda_bf16.h>
#include <cstdint>

#define B_USERS 2048
#define P_POSTS 16384
#define LEN     50
#define D_EMB   300
#define NFILT   100
#define HID     64
#define INF_    768

#define DC16    19             // ceil(300/16) k-chunks of 16
#define WROWS   52             // 48 positions + max kk shift 4
#define WSTRIDE 156            // 32-bit words per row (312 bf16 >= 304); 156%32=28 -> conflict-free
#define USZ     (WROWS * WSTRIDE)   // 8112 words per user per (hi|lo)

// fragment counts (13 n8 tiles per group)
#define FRG0    (13 * 3 * DC16)     // 741
#define FRG1    (13 * 4 * DC16)     // 988
#define FRG2    (13 * 5 * DC16)     // 1235
#define NFRAG   (FRG0 + FRG1 + FRG2)  // 2964

// ---------------- scratch (device globals; no allocation) ----------------
__device__ int    g_segstart[B_USERS + 1];
__device__ float  g_hist[(size_t)B_USERS * LEN * D_EMB];   // [B, 50, 300]
__device__ float  g_rec[B_USERS * HID];
__device__ uint4  g_wf[NFRAG * 32];     // W frags: {hi_b0, hi_b1, lo_b0, lo_b1} per lane
__device__ float  g_hwt[300 * 64];      // hist_w transposed [j][o]
__device__ float  g_w1t[INF_ * 128];    // fc_w1 transposed [d][o]
__device__ float  g_w2t[128 * 64];      // fc_w2 transposed [d][j]

// ---------------- job scheduling tables ----------------
struct Job { int8_t u, g, nb0, cnt; };
__constant__ Job c_jobs[20] = {
    // user 0
    {0,2,0,4},{0,2,4,4},{0,2,8,4},{0,2,12,1},{0,1,0,5},
    {0,1,5,4},{0,1,9,4},{0,0,0,5},{0,0,5,4},{0,0,9,4},
    // user 1
    {1,2,0,4},{1,2,4,4},{1,2,8,4},{1,2,12,1},{1,1,0,5},
    {1,1,5,4},{1,1,9,4},{1,0,0,5},{1,0,5,4},{1,0,9,4},
};
__constant__ int8_t c_warp[16][2] = {
    {0,-1},{1,-1},{2,-1},{4,-1},{10,-1},{11,-1},{12,-1},{14,-1},
    {5,-1},{6,-1},{15,-1},{16,-1},{7,3},{17,13},{8,9},{18,19},
};

__device__ __forceinline__ uint32_t pack_bf16(float a, float b) {
    __nv_bfloat16 ha = __float2bfloat16_rn(a);
    __nv_bfloat16 hb = __float2bfloat16_rn(b);
    return ((uint32_t)__bfloat16_as_ushort(hb) << 16) | __bfloat16_as_ushort(ha);
}

#define MMA_BF16(c, a, b0, b1)                                                  \
    asm("mma.sync.aligned.m16n8k16.row.col.f32.bf16.bf16.f32 "                  \
        "{%0,%1,%2,%3},{%4,%5,%6,%7},{%8,%9},{%0,%1,%2,%3};"                    \
        : "+f"(c[0]), "+f"(c[1]), "+f"(c[2]), "+f"(c[3])                         \
        : "r"(a[0]), "r"(a[1]), "r"(a[2]), "r"(a[3]), "r"(b0), "r"(b1))

// ---------------- kernel A: segment offsets ----------------
__global__ void seg_bounds_kernel(const int* __restrict__ seg_ids) {
    int b = blockIdx.x * blockDim.x + threadIdx.x;
    if (b > B_USERS) return;
    int lo = 0, hi = P_POSTS;
    while (lo < hi) {
        int mid = (lo + hi) >> 1;
        if (seg_ids[mid] < b) lo = mid + 1; else hi = mid;
    }
    g_segstart[b] = lo;
}

// ---------------- prep: bf16 hi/lo W fragments + small transposes ----------------
__global__ void prep_kernel(const float* __restrict__ w3, const float* __restrict__ w4,
                            const float* __restrict__ w5, const float* __restrict__ hw_,
                            const float* __restrict__ w1, const float* __restrict__ w2) {
    int idx = blockIdx.x * 256 + threadIdx.x;
    if (idx < NFRAG * 32) {
        int lane = idx & 31;
        int frag = idx >> 5;
        int Kg; const float* w; int rel;
        if (frag < FRG0)               { Kg = 3; w = w3; rel = frag; }
        else if (frag < FRG0 + FRG1)   { Kg = 4; w = w4; rel = frag - FRG0; }
        else                           { Kg = 5; w = w5; rel = frag - FRG0 - FRG1; }
        int nb = rel / (Kg * DC16);
        int r2 = rel - nb * (Kg * DC16);
        int kk = r2 / DC16;
        int dc = r2 - kk * DC16;
        int n  = lane >> 2;
        int t  = lane & 3;
        int f  = nb * 8 + n;
        float v[4] = {0.f, 0.f, 0.f, 0.f};
        int dk[4] = {2*t, 2*t+1, 2*t+8, 2*t+9};
        if (f < NFILT) {
#pragma unroll
            for (int e = 0; e < 4; ++e) {
                int d = dc * 16 + dk[e];
                if (d < D_EMB) v[e] = __ldg(w + (f * D_EMB + d) * Kg + kk);
            }
        }
        float h[4], l[4];
#pragma unroll
        for (int e = 0; e < 4; ++e) {
            __nv_bfloat16 hb = __float2bfloat16_rn(v[e]);
            h[e] = __bfloat162float(hb);
            l[e] = v[e] - h[e];
        }
        uint4 out;
        out.x = pack_bf16(h[0], h[1]);
        out.y = pack_bf16(h[2], h[3]);
        out.z = pack_bf16(l[0], l[1]);
        out.w = pack_bf16(l[2], l[3]);
        g_wf[frag * 32 + lane] = out;
        return;
    }
    int i2 = idx - NFRAG * 32;                 // g_hwt: 300*64
    if (i2 >= 0 && i2 < 300 * 64) {
        int o = i2 & 63; int j = i2 >> 6;
        g_hwt[i2] = __ldg(hw_ + o * 300 + j);
        return;
    }
    int i3 = i2 - 300 * 64;                    // g_w1t: 768*128
    if (i3 >= 0 && i3 < INF_ * 128) {
        int o = i3 & 127; int d = i3 >> 7;
        g_w1t[i3] = __ldg(w1 + o * INF_ + d);
        return;
    }
    int i4 = i3 - INF_ * 128;                  // g_w2t: 128*64
    if (i4 >= 0 && i4 < 128 * 64) {
        int j = i4 & 63; int d = i4 >> 6;
        g_w2t[i4] = __ldg(w2 + j * 128 + d);
    }
}

// ---------------- kernel B: segment-mean of embeddings -> g_hist ----------------
__global__ void hist_kernel(const int* __restrict__ tokens,
                            const float* __restrict__ emb) {
    int l = blockIdx.x;
    int b = blockIdx.y;
    int tid = threadIdx.x;
    int s = g_segstart[b], e = g_segstart[b + 1];

    float a0 = 0.f, a1 = 0.f, a2 = 0.f;
    float c0 = 0.f, c1 = 0.f, c2 = 0.f;
    int p = s;
    for (; p + 1 < e; p += 2) {
        int t0 = __ldg(tokens + p * LEN + l);
        int t1 = __ldg(tokens + (p + 1) * LEN + l);
        const float* r0 = emb + (size_t)t0 * D_EMB;
        const float* r1 = emb + (size_t)t1 * D_EMB;
        a0 += __ldg(r0 + tid);        c0 += __ldg(r1 + tid);
        a1 += __ldg(r0 + tid + 128);  c1 += __ldg(r1 + tid + 128);
        if (tid < 44) { a2 += __ldg(r0 + tid + 256); c2 += __ldg(r1 + tid + 256); }
    }
    if (p < e) {
        int t0 = __ldg(tokens + p * LEN + l);
        const float* r0 = emb + (size_t)t0 * D_EMB;
        a0 += __ldg(r0 + tid);
        a1 += __ldg(r0 + tid + 128);
        if (tid < 44) a2 += __ldg(r0 + tid + 256);
    }
    float scale = 1.0f / (float)max(e - s, 1);
    float* o = g_hist + ((size_t)b * LEN + l) * D_EMB;
    o[tid]       = (a0 + c0) * scale;
    o[tid + 128] = (a1 + c1) * scale;
    if (tid < 44) o[tid + 256] = (a2 + c2) * scale;
}

// ---------------- conv job: one (g, nb-range) tile column strip, bf16x3 ----------------
template <int CNT>
__device__ __forceinline__ void conv_job(const uint32_t* __restrict__ shi,
                                         const uint32_t* __restrict__ slo,
                                         int Kg, int gbase, int nb0, int Tg,
                                         const float* __restrict__ bp,
                                         float* __restrict__ sf) {
    int lane = threadIdx.x & 31;
    int g8   = lane >> 2;
    int t    = lane & 3;

    float acc[3][CNT][4];
#pragma unroll
    for (int mt = 0; mt < 3; ++mt)
#pragma unroll
        for (int j = 0; j < CNT; ++j)
#pragma unroll
            for (int c = 0; c < 4; ++c) acc[mt][j][c] = 0.f;

    for (int kk = 0; kk < Kg; ++kk) {
        int rowbase = g8 + kk;
        const uint4* fptr = g_wf + (size_t)(gbase + (nb0 * Kg + kk) * DC16) * 32 + lane;
        for (int dc = 0; dc < DC16; ++dc) {
            uint32_t ah[3][4], al[3][4];
#pragma unroll
            for (int mt = 0; mt < 3; ++mt) {
                int r0 = rowbase + mt * 16;
                int w0 = dc * 8 + t;
                ah[mt][0] = shi[r0 * WSTRIDE + w0];
                ah[mt][1] = shi[(r0 + 8) * WSTRIDE + w0];
                ah[mt][2] = shi[r0 * WSTRIDE + w0 + 4];
                ah[mt][3] = shi[(r0 + 8) * WSTRIDE + w0 + 4];
                al[mt][0] = slo[r0 * WSTRIDE + w0];
                al[mt][1] = slo[(r0 + 8) * WSTRIDE + w0];
                al[mt][2] = slo[r0 * WSTRIDE + w0 + 4];
                al[mt][3] = slo[(r0 + 8) * WSTRIDE + w0 + 4];
            }
#pragma unroll
            for (int j = 0; j < CNT; ++j) {
                uint4 wv = __ldg(fptr + (size_t)j * (Kg * DC16) * 32 + dc * 32);
#pragma unroll
                for (int mt = 0; mt < 3; ++mt) {
                    MMA_BF16(acc[mt][j], ah[mt], wv.x, wv.y);   // hi*hi
                    MMA_BF16(acc[mt][j], ah[mt], wv.z, wv.w);   // hi*lo
                    MMA_BF16(acc[mt][j], al[mt], wv.x, wv.y);   // lo*hi
                }
            }
        }
    }

    // masked max-pool over positions, reduce across g8, write feats
#pragma unroll
    for (int j = 0; j < CNT; ++j) {
        float m0 = -1e30f, m1 = -1e30f;
#pragma unroll
        for (int mt = 0; mt < 3; ++mt) {
            int p0 = mt * 16 + g8;
            int p1 = p0 + 8;
            if (p0 < Tg) { m0 = fmaxf(m0, acc[mt][j][0]); m1 = fmaxf(m1, acc[mt][j][1]); }
            if (p1 < Tg) { m0 = fmaxf(m0, acc[mt][j][2]); m1 = fmaxf(m1, acc[mt][j][3]); }
        }
#pragma unroll
        for (int off = 4; off < 32; off <<= 1) {
            m0 = fmaxf(m0, __shfl_xor_sync(0xffffffff, m0, off));
            m1 = fmaxf(m1, __shfl_xor_sync(0xffffffff, m1, off));
        }
        if (g8 == 0) {
            int f0 = (nb0 + j) * 8 + 2 * t;
            if (f0 < NFILT)     sf[f0]     = fmaxf(m0 + __ldg(bp + f0), 0.f);
            if (f0 + 1 < NFILT) sf[f0 + 1] = fmaxf(m1 + __ldg(bp + f0 + 1), 0.f);
        }
    }
}

// ---------------- kernel C: TextCNN via bf16x3 tensor cores ----------------
__global__ void __launch_bounds__(512, 1)
conv_mma_kernel(const float* __restrict__ b3, const float* __restrict__ b4,
                const float* __restrict__ b5, const float* __restrict__ hb_) {
    extern __shared__ uint32_t shw[];           // [hi u0][hi u1][lo u0][lo u1][feats]
    float* feats = (float*)(shw + 4 * USZ);
    int tid = threadIdx.x;
    int b0  = blockIdx.x * 2;

    // load 2 users' hist, split into bf16 hi/lo, pack pairs
    for (int i = tid; i < 2 * USZ; i += 512) {
        int u   = i / USZ;
        int idx = i - u * USZ;
        int r   = idx / WSTRIDE;
        int w   = idx - r * WSTRIDE;
        int col = w * 2;
        float x0 = 0.f, x1 = 0.f;
        if (r < LEN && col < D_EMB) {
            const float* src = g_hist + (((size_t)(b0 + u)) * LEN + r) * D_EMB;
            x0 = src[col];
            if (col + 1 < D_EMB) x1 = src[col + 1];
        }
        __nv_bfloat16 h0 = __float2bfloat16_rn(x0);
        __nv_bfloat16 h1 = __float2bfloat16_rn(x1);
        float l0f = x0 - __bfloat162float(h0);
        float l1f = x1 - __bfloat162float(h1);
        shw[u * USZ + idx] = ((uint32_t)__bfloat16_as_ushort(h1) << 16) |
                             __bfloat16_as_ushort(h0);
        shw[2 * USZ + u * USZ + idx] = pack_bf16(l0f, l1f);
    }
    __syncthreads();

    int warpid = tid >> 5;
#pragma unroll
    for (int slot = 0; slot < 2; ++slot) {
        int jid = c_warp[warpid][slot];
        if (jid < 0) continue;
        Job jb = c_jobs[jid];
        int u  = jb.u, g = jb.g, nb0 = jb.nb0, cnt = jb.cnt;
        int Kg = 3 + g;
        int gbase = (g == 0) ? 0 : ((g == 1) ? FRG0 : (FRG0 + FRG1));
        int Tg = 51 - Kg;                        // 48 / 47 / 46
        const float* bp = (g == 0) ? b3 : ((g == 1) ? b4 : b5);
        const uint32_t* shi = shw + u * USZ;
        const uint32_t* slo = shw + 2 * USZ + u * USZ;
        float* sf = feats + u * 300 + g * 100;
        if (cnt == 5)      conv_job<5>(shi, slo, Kg, gbase, nb0, Tg, bp, sf);
        else if (cnt == 4) conv_job<4>(shi, slo, Kg, gbase, nb0, Tg, bp, sf);
        else               conv_job<1>(shi, slo, Kg, gbase, nb0, Tg, bp, sf);
    }
    __syncthreads();

    // rec GEMM: [2 users] x [300 feats] x [64 outs]
    if (tid < 128) {
        int u = tid >> 6;
        int o = tid & 63;
        const float* sf = feats + u * 300;
        float r = __ldg(hb_ + o);
#pragma unroll 4
        for (int j = 0; j < 300; ++j)
            r = fmaf(sf[j], __ldg(g_hwt + j * HID + o), r);
        g_rec[(b0 + u) * HID + o] = r;
    }
}

// ---------------- kernel D: fc_out on root features + final add ----------------
#define TB 8
__global__ void __launch_bounds__(256)
fc_kernel(const float* __restrict__ x, const int* __restrict__ root,
          const float* __restrict__ b1, const float* __restrict__ b2,
          float* __restrict__ out) {
    __shared__ float sx[TB * INF_];
    __shared__ float hh[TB * 128];
    __shared__ int   ridx[TB];
    int tid = threadIdx.x;
    int b0 = blockIdx.x * TB;

    if (tid < TB) ridx[tid] = __ldg(root + b0 + tid);
    __syncthreads();
    for (int i = tid; i < TB * INF_; i += 256) {
        int u = i / INF_; int d = i - u * INF_;
        sx[i] = __ldg(x + (size_t)ridx[u] * INF_ + d);
    }
    __syncthreads();

    {
        int o  = tid & 127;
        int ug = tid >> 7;
        float acc[4] = {0.f, 0.f, 0.f, 0.f};
        for (int d = 0; d < INF_; ++d) {
            float wv = __ldg(g_w1t + d * 128 + o);
#pragma unroll
            for (int uu = 0; uu < 4; ++uu)
                acc[uu] = fmaf(sx[(ug * 4 + uu) * INF_ + d], wv, acc[uu]);
        }
        float bb = __ldg(b1 + o);
#pragma unroll
        for (int uu = 0; uu < 4; ++uu)
            hh[(ug * 4 + uu) * 128 + o] = fmaxf(acc[uu] + bb, 0.f);
    }
    __syncthreads();

    {
        int j = tid & 63;
        int q = tid >> 6;
        int u0 = 2 * q, u1 = 2 * q + 1;
        float a0 = 0.f, a1 = 0.f;
        for (int d = 0; d < 128; ++d) {
            float wv = __ldg(g_w2t + d * 64 + j);
            a0 = fmaf(hh[u0 * 128 + d], wv, a0);
            a1 = fmaf(hh[u1 * 128 + d], wv, a1);
        }
        float bb = __ldg(b2 + j);
        out[(b0 + u0) * HID + j] = a0 + bb + g_rec[(b0 + u0) * HID + j];
        out[(b0 + u1) * HID + j] = a1 + bb + g_rec[(b0 + u1) * HID + j];
    }
}

// ---------------- launch ----------------
extern "C" void kernel_launch(void* const* d_in, const int* in_sizes, int n_in,
                              void* d_out, int out_size) {
    const float* x        = (const float*)d_in[0];
    const int*   root     = (const int*)  d_in[1];
    const int*   tokens   = (const int*)  d_in[2];
    const int*   seg_ids  = (const int*)  d_in[3];
    const float* emb      = (const float*)d_in[4];
    const float* w3 = (const float*)d_in[5];   const float* b3 = (const float*)d_in[6];
    const float* w4 = (const float*)d_in[7];   const float* b4 = (const float*)d_in[8];
    const float* w5 = (const float*)d_in[9];   const float* b5 = (const float*)d_in[10];
    const float* hw = (const float*)d_in[11];  const float* hb = (const float*)d_in[12];
    const float* f1w = (const float*)d_in[13]; const float* f1b = (const float*)d_in[14];
    const float* f2w = (const float*)d_in[15]; const float* f2b = (const float*)d_in[16];
    float* out = (float*)d_out;

    const int conv_smem = (4 * USZ + 600) * (int)sizeof(uint32_t);  // ~132.2 KB
    cudaFuncSetAttribute(conv_mma_kernel, cudaFuncAttributeMaxDynamicSharedMemorySize,
                         conv_smem);

    int prep_threads = NFRAG * 32 + 300 * 64 + INF_ * 128 + 128 * 64;
    seg_bounds_kernel<<<(B_USERS + 1 + 255) / 256, 256>>>(seg_ids);
    prep_kernel<<<(prep_threads + 255) / 256, 256>>>(w3, w4, w5, hw, f1w, f2w);
    {
        dim3 grid(LEN, B_USERS);
        hist_kernel<<<grid, 128>>>(tokens, emb);
    }
    conv_mma_kernel<<<B_USERS / 2, 512, conv_smem>>>(b3, b4, b5, hb);
    fc_kernel<<<B_USERS / TB, 256>>>(x, root, f1b, f2b, out);
}

// round 7
// speedup vs baseline: 4.1495x; 1.0671x over previous
#include <cuda_runtime.h>
#include <cuda_bf16.h>
#include <cstdint>

#define B_USERS 2048
#define P_POSTS 16384
#define LEN     50
#define D_EMB   300
#define NFILT   100
#define HID     64
#define INF_    768

#define DC16    19             // ceil(300/16) k-chunks of 16
#define WROWS   52             // 48 positions + max kk shift 4
#define WSTRIDE 156            // words per row; 156%32=28 -> ldmatrix conflict-free
#define USZ     (WROWS * WSTRIDE)   // 8112 words per user per (hi|lo)

// fragment counts (13 n8 tiles per group)
#define FRG0    (13 * 3 * DC16)     // 741
#define FRG1    (13 * 4 * DC16)     // 988
#define FRG2    (13 * 5 * DC16)     // 1235
#define NFRAG   (FRG0 + FRG1 + FRG2)  // 2964

// ---------------- scratch (device globals; no allocation) ----------------
__device__ int    g_segstart[B_USERS + 1];
__device__ float  g_hist[(size_t)B_USERS * LEN * D_EMB];   // [B, 50, 300]
__device__ float  g_rec[B_USERS * HID];
__device__ uint4  g_wf[NFRAG * 32];     // W frags: {hi_b0, hi_b1, lo_b0, lo_b1} per lane
__device__ float  g_hwt[300 * 64];      // hist_w transposed [j][o]
__device__ float  g_w1t[INF_ * 128];    // fc_w1 transposed [d][o]
__device__ float  g_w2t[128 * 64];      // fc_w2 transposed [d][j]

// ---------------- balanced job table: 8 slots/user, cost 20/20/20/20/20/20/18/18 ----------------
struct Job { int8_t g, nb0, cnt; };
__constant__ Job c_slots[8][2] = {
    {{2, 0, 4}, {-1, 0, 0}},
    {{2, 4, 4}, {-1, 0, 0}},
    {{2, 8, 4}, {-1, 0, 0}},
    {{2,12, 1}, { 0, 0, 5}},
    {{1, 0, 5}, {-1, 0, 0}},
    {{1, 5, 5}, {-1, 0, 0}},
    {{1,10, 3}, { 0, 5, 2}},
    {{0, 7, 3}, { 0,10, 3}},
};

__device__ __forceinline__ uint32_t pack_bf16(float a, float b) {
    __nv_bfloat16 ha = __float2bfloat16_rn(a);
    __nv_bfloat16 hb = __float2bfloat16_rn(b);
    return ((uint32_t)__bfloat16_as_ushort(hb) << 16) | __bfloat16_as_ushort(ha);
}

#define MMA_BF16(c, a, b0, b1)                                                  \
    asm("mma.sync.aligned.m16n8k16.row.col.f32.bf16.bf16.f32 "                  \
        "{%0,%1,%2,%3},{%4,%5,%6,%7},{%8,%9},{%0,%1,%2,%3};"                    \
        : "+f"(c[0]), "+f"(c[1]), "+f"(c[2]), "+f"(c[3])                         \
        : "r"(a[0]), "r"(a[1]), "r"(a[2]), "r"(a[3]), "r"(b0), "r"(b1))

__device__ __forceinline__ void ldsm4(uint32_t* r, const uint32_t* p) {
    uint32_t addr = (uint32_t)__cvta_generic_to_shared(p);
    asm volatile("ldmatrix.sync.aligned.m8n8.x4.shared.b16 {%0,%1,%2,%3}, [%4];"
                 : "=r"(r[0]), "=r"(r[1]), "=r"(r[2]), "=r"(r[3]) : "r"(addr));
}

// ---------------- kernel A: segment offsets ----------------
__global__ void seg_bounds_kernel(const int* __restrict__ seg_ids) {
    int b = blockIdx.x * blockDim.x + threadIdx.x;
    if (b > B_USERS) return;
    int lo = 0, hi = P_POSTS;
    while (lo < hi) {
        int mid = (lo + hi) >> 1;
        if (seg_ids[mid] < b) lo = mid + 1; else hi = mid;
    }
    g_segstart[b] = lo;
}

// ---------------- prep: bf16 hi/lo W fragments + small transposes ----------------
__global__ void prep_kernel(const float* __restrict__ w3, const float* __restrict__ w4,
                            const float* __restrict__ w5, const float* __restrict__ hw_,
                            const float* __restrict__ w1, const float* __restrict__ w2) {
    int idx = blockIdx.x * 256 + threadIdx.x;
    if (idx < NFRAG * 32) {
        int lane = idx & 31;
        int frag = idx >> 5;
        int Kg; const float* w; int rel;
        if (frag < FRG0)               { Kg = 3; w = w3; rel = frag; }
        else if (frag < FRG0 + FRG1)   { Kg = 4; w = w4; rel = frag - FRG0; }
        else                           { Kg = 5; w = w5; rel = frag - FRG0 - FRG1; }
        int nb = rel / (Kg * DC16);
        int r2 = rel - nb * (Kg * DC16);
        int kk = r2 / DC16;
        int dc = r2 - kk * DC16;
        int n  = lane >> 2;
        int t  = lane & 3;
        int f  = nb * 8 + n;
        float v[4] = {0.f, 0.f, 0.f, 0.f};
        int dk[4] = {2*t, 2*t+1, 2*t+8, 2*t+9};
        if (f < NFILT) {
#pragma unroll
            for (int e = 0; e < 4; ++e) {
                int d = dc * 16 + dk[e];
                if (d < D_EMB) v[e] = __ldg(w + (f * D_EMB + d) * Kg + kk);
            }
        }
        float h[4], l[4];
#pragma unroll
        for (int e = 0; e < 4; ++e) {
            __nv_bfloat16 hb = __float2bfloat16_rn(v[e]);
            h[e] = __bfloat162float(hb);
            l[e] = v[e] - h[e];
        }
        uint4 out;
        out.x = pack_bf16(h[0], h[1]);
        out.y = pack_bf16(h[2], h[3]);
        out.z = pack_bf16(l[0], l[1]);
        out.w = pack_bf16(l[2], l[3]);
        g_wf[frag * 32 + lane] = out;
        return;
    }
    int i2 = idx - NFRAG * 32;                 // g_hwt: 300*64
    if (i2 >= 0 && i2 < 300 * 64) {
        int o = i2 & 63; int j = i2 >> 6;
        g_hwt[i2] = __ldg(hw_ + o * 300 + j);
        return;
    }
    int i3 = i2 - 300 * 64;                    // g_w1t: 768*128
    if (i3 >= 0 && i3 < INF_ * 128) {
        int o = i3 & 127; int d = i3 >> 7;
        g_w1t[i3] = __ldg(w1 + o * INF_ + d);
        return;
    }
    int i4 = i3 - INF_ * 128;                  // g_w2t: 128*64
    if (i4 >= 0 && i4 < 128 * 64) {
        int j = i4 & 63; int d = i4 >> 6;
        g_w2t[i4] = __ldg(w2 + j * 128 + d);
    }
}

// ---------------- kernel B: segment-mean of embeddings (float4) ----------------
__global__ void __launch_bounds__(96)
hist_kernel(const int* __restrict__ tokens, const float* __restrict__ emb) {
    int l = blockIdx.x;
    int b = blockIdx.y;
    int t = threadIdx.x;
    if (t >= 75) return;                     // 75 float4 = 300 floats
    int s = g_segstart[b], e = g_segstart[b + 1];

    float4 a = {0.f, 0.f, 0.f, 0.f};
    float4 c = {0.f, 0.f, 0.f, 0.f};
    int p = s;
    for (; p + 1 < e; p += 2) {
        int t0 = __ldg(tokens + p * LEN + l);
        int t1 = __ldg(tokens + (p + 1) * LEN + l);
        float4 v0 = __ldg((const float4*)(emb + (size_t)t0 * D_EMB) + t);
        float4 v1 = __ldg((const float4*)(emb + (size_t)t1 * D_EMB) + t);
        a.x += v0.x; a.y += v0.y; a.z += v0.z; a.w += v0.w;
        c.x += v1.x; c.y += v1.y; c.z += v1.z; c.w += v1.w;
    }
    if (p < e) {
        int t0 = __ldg(tokens + p * LEN + l);
        float4 v0 = __ldg((const float4*)(emb + (size_t)t0 * D_EMB) + t);
        a.x += v0.x; a.y += v0.y; a.z += v0.z; a.w += v0.w;
    }
    float sc = 1.0f / (float)max(e - s, 1);
    float4 o;
    o.x = (a.x + c.x) * sc; o.y = (a.y + c.y) * sc;
    o.z = (a.z + c.z) * sc; o.w = (a.w + c.w) * sc;
    ((float4*)(g_hist + ((size_t)b * LEN + l) * D_EMB))[t] = o;
}

// ---------------- conv job: ldmatrix A frags + pass-major bf16x3 mma ----------------
template <int CNT>
__device__ __forceinline__ void conv_job(const uint32_t* __restrict__ shi,
                                         const uint32_t* __restrict__ slo,
                                         int Kg, int gbase, int nb0, int Tg,
                                         const float* __restrict__ bp,
                                         float* __restrict__ sf) {
    int lane = threadIdx.x & 31;
    int g8   = lane >> 2;
    int t    = lane & 3;
    // ldmatrix per-lane address selectors
    int lr     = lane & 7;
    int sel    = lane >> 3;
    int rowsel = lr + ((sel & 1) << 3);      // row within 16-row tile
    int colsel = (sel & 2) << 1;             // +0 / +4 words (k halves)

    float acc[3][CNT][4];
#pragma unroll
    for (int mt = 0; mt < 3; ++mt)
#pragma unroll
        for (int j = 0; j < CNT; ++j)
#pragma unroll
            for (int c = 0; c < 4; ++c) acc[mt][j][c] = 0.f;

    for (int kk = 0; kk < Kg; ++kk) {
        const uint4* fptr = g_wf + (size_t)(gbase + (nb0 * Kg + kk) * DC16) * 32 + lane;
        int rbase = kk + rowsel;
        for (int dc = 0; dc < DC16; ++dc) {
            uint4 wv[CNT];
#pragma unroll
            for (int j = 0; j < CNT; ++j)
                wv[j] = __ldg(fptr + (size_t)j * (Kg * DC16) * 32 + dc * 32);

            uint32_t ah[3][4], al[3][4];
            int widx = dc * 8 + colsel;
#pragma unroll
            for (int mt = 0; mt < 3; ++mt) {
                const uint32_t* pa = shi + (mt * 16 + rbase) * WSTRIDE + widx;
                const uint32_t* pl = slo + (mt * 16 + rbase) * WSTRIDE + widx;
                ldsm4(ah[mt], pa);
                ldsm4(al[mt], pl);
            }
            // pass-major: same-acc reuse distance = 3*CNT
#pragma unroll
            for (int j = 0; j < CNT; ++j)
#pragma unroll
                for (int mt = 0; mt < 3; ++mt)
                    MMA_BF16(acc[mt][j], ah[mt], wv[j].x, wv[j].y);   // hi*hi
#pragma unroll
            for (int j = 0; j < CNT; ++j)
#pragma unroll
                for (int mt = 0; mt < 3; ++mt)
                    MMA_BF16(acc[mt][j], ah[mt], wv[j].z, wv[j].w);   // hi*lo
#pragma unroll
            for (int j = 0; j < CNT; ++j)
#pragma unroll
                for (int mt = 0; mt < 3; ++mt)
                    MMA_BF16(acc[mt][j], al[mt], wv[j].x, wv[j].y);   // lo*hi
        }
    }

    // masked max-pool over positions, reduce across g8, write feats
#pragma unroll
    for (int j = 0; j < CNT; ++j) {
        float m0 = -1e30f, m1 = -1e30f;
#pragma unroll
        for (int mt = 0; mt < 3; ++mt) {
            int p0 = mt * 16 + g8;
            int p1 = p0 + 8;
            if (p0 < Tg) { m0 = fmaxf(m0, acc[mt][j][0]); m1 = fmaxf(m1, acc[mt][j][1]); }
            if (p1 < Tg) { m0 = fmaxf(m0, acc[mt][j][2]); m1 = fmaxf(m1, acc[mt][j][3]); }
        }
#pragma unroll
        for (int off = 4; off < 32; off <<= 1) {
            m0 = fmaxf(m0, __shfl_xor_sync(0xffffffff, m0, off));
            m1 = fmaxf(m1, __shfl_xor_sync(0xffffffff, m1, off));
        }
        if (g8 == 0) {
            int f0 = (nb0 + j) * 8 + 2 * t;
            if (f0 < NFILT)     sf[f0]     = fmaxf(m0 + __ldg(bp + f0), 0.f);
            if (f0 + 1 < NFILT) sf[f0 + 1] = fmaxf(m1 + __ldg(bp + f0 + 1), 0.f);
        }
    }
}

__device__ __forceinline__ void run_job(const uint32_t* shi, const uint32_t* slo,
                                        int g, int nb0, int cnt,
                                        const float* b3, const float* b4,
                                        const float* b5, float* feats_u) {
    int Kg = 3 + g;
    int gbase = (g == 0) ? 0 : ((g == 1) ? FRG0 : (FRG0 + FRG1));
    int Tg = 51 - Kg;
    const float* bp = (g == 0) ? b3 : ((g == 1) ? b4 : b5);
    float* sf = feats_u + g * 100;
    switch (cnt) {
        case 5: conv_job<5>(shi, slo, Kg, gbase, nb0, Tg, bp, sf); break;
        case 4: conv_job<4>(shi, slo, Kg, gbase, nb0, Tg, bp, sf); break;
        case 3: conv_job<3>(shi, slo, Kg, gbase, nb0, Tg, bp, sf); break;
        case 2: conv_job<2>(shi, slo, Kg, gbase, nb0, Tg, bp, sf); break;
        default: conv_job<1>(shi, slo, Kg, gbase, nb0, Tg, bp, sf); break;
    }
}

// ---------------- kernel C: TextCNN via bf16x3 tensor cores ----------------
__global__ void __launch_bounds__(512, 1)
conv_mma_kernel(const float* __restrict__ b3, const float* __restrict__ b4,
                const float* __restrict__ b5, const float* __restrict__ hb_) {
    extern __shared__ uint32_t shw[];           // [hi u0][hi u1][lo u0][lo u1][feats]
    float* feats = (float*)(shw + 4 * USZ);
    int tid = threadIdx.x;
    int b0  = blockIdx.x * 2;

    // load 2 users' hist, split into bf16 hi/lo, pack pairs
    for (int i = tid; i < 2 * USZ; i += 512) {
        int u   = i / USZ;
        int idx = i - u * USZ;
        int r   = idx / WSTRIDE;
        int w   = idx - r * WSTRIDE;
        int col = w * 2;
        float x0 = 0.f, x1 = 0.f;
        if (r < LEN && col < D_EMB) {
            const float* src = g_hist + (((size_t)(b0 + u)) * LEN + r) * D_EMB;
            x0 = src[col];
            if (col + 1 < D_EMB) x1 = src[col + 1];
        }
        __nv_bfloat16 h0 = __float2bfloat16_rn(x0);
        __nv_bfloat16 h1 = __float2bfloat16_rn(x1);
        float l0f = x0 - __bfloat162float(h0);
        float l1f = x1 - __bfloat162float(h1);
        shw[u * USZ + idx] = ((uint32_t)__bfloat16_as_ushort(h1) << 16) |
                             __bfloat16_as_ushort(h0);
        shw[2 * USZ + u * USZ + idx] = pack_bf16(l0f, l1f);
    }
    __syncthreads();

    int warpid = tid >> 5;
    int u      = warpid >> 3;
    int slot   = warpid & 7;
    const uint32_t* shi = shw + u * USZ;
    const uint32_t* slo = shw + 2 * USZ + u * USZ;
    float* feats_u = feats + u * 300;

#pragma unroll
    for (int q = 0; q < 2; ++q) {
        Job jb = c_slots[slot][q];
        if (jb.g < 0) continue;
        run_job(shi, slo, jb.g, jb.nb0, jb.cnt, b3, b4, b5, feats_u);
    }
    __syncthreads();

    // rec GEMM: [2 users] x [300 feats] x [64 outs]
    if (tid < 128) {
        int uu = tid >> 6;
        int o  = tid & 63;
        const float* sf = feats + uu * 300;
        float r = __ldg(hb_ + o);
#pragma unroll 4
        for (int j = 0; j < 300; ++j)
            r = fmaf(sf[j], __ldg(g_hwt + j * HID + o), r);
        g_rec[(b0 + uu) * HID + o] = r;
    }
}

// ---------------- kernel D: fc_out on root features + final add ----------------
#define TB 8
__global__ void __launch_bounds__(256)
fc_kernel(const float* __restrict__ x, const int* __restrict__ root,
          const float* __restrict__ b1, const float* __restrict__ b2,
          float* __restrict__ out) {
    __shared__ float sx[TB * INF_];
    __shared__ float hh[TB * 128];
    __shared__ int   ridx[TB];
    int tid = threadIdx.x;
    int b0 = blockIdx.x * TB;

    if (tid < TB) ridx[tid] = __ldg(root + b0 + tid);
    __syncthreads();
    for (int i = tid; i < TB * INF_; i += 256) {
        int u = i / INF_; int d = i - u * INF_;
        sx[i] = __ldg(x + (size_t)ridx[u] * INF_ + d);
    }
    __syncthreads();

    {
        int o  = tid & 127;
        int ug = tid >> 7;
        float acc[4] = {0.f, 0.f, 0.f, 0.f};
        for (int d = 0; d < INF_; ++d) {
            float wv = __ldg(g_w1t + d * 128 + o);
#pragma unroll
            for (int uu = 0; uu < 4; ++uu)
                acc[uu] = fmaf(sx[(ug * 4 + uu) * INF_ + d], wv, acc[uu]);
        }
        float bb = __ldg(b1 + o);
#pragma unroll
        for (int uu = 0; uu < 4; ++uu)
            hh[(ug * 4 + uu) * 128 + o] = fmaxf(acc[uu] + bb, 0.f);
    }
    __syncthreads();

    {
        int j = tid & 63;
        int q = tid >> 6;
        int u0 = 2 * q, u1 = 2 * q + 1;
        float a0 = 0.f, a1 = 0.f;
        for (int d = 0; d < 128; ++d) {
            float wv = __ldg(g_w2t + d * 64 + j);
            a0 = fmaf(hh[u0 * 128 + d], wv, a0);
            a1 = fmaf(hh[u1 * 128 + d], wv, a1);
        }
        float bb = __ldg(b2 + j);
        out[(b0 + u0) * HID + j] = a0 + bb + g_rec[(b0 + u0) * HID + j];
        out[(b0 + u1) * HID + j] = a1 + bb + g_rec[(b0 + u1) * HID + j];
    }
}

// ---------------- launch ----------------
extern "C" void kernel_launch(void* const* d_in, const int* in_sizes, int n_in,
                              void* d_out, int out_size) {
    const float* x        = (const float*)d_in[0];
    const int*   root     = (const int*)  d_in[1];
    const int*   tokens   = (const int*)  d_in[2];
    const int*   seg_ids  = (const int*)  d_in[3];
    const float* emb      = (const float*)d_in[4];
    const float* w3 = (const float*)d_in[5];   const float* b3 = (const float*)d_in[6];
    const float* w4 = (const float*)d_in[7];   const float* b4 = (const float*)d_in[8];
    const float* w5 = (const float*)d_in[9];   const float* b5 = (const float*)d_in[10];
    const float* hw = (const float*)d_in[11];  const float* hb = (const float*)d_in[12];
    const float* f1w = (const float*)d_in[13]; const float* f1b = (const float*)d_in[14];
    const float* f2w = (const float*)d_in[15]; const float* f2b = (const float*)d_in[16];
    float* out = (float*)d_out;

    const int conv_smem = (4 * USZ + 600) * (int)sizeof(uint32_t);  // ~132.2 KB
    cudaFuncSetAttribute(conv_mma_kernel, cudaFuncAttributeMaxDynamicSharedMemorySize,
                         conv_smem);

    int prep_threads = NFRAG * 32 + 300 * 64 + INF_ * 128 + 128 * 64;
    seg_bounds_kernel<<<(B_USERS + 1 + 255) / 256, 256>>>(seg_ids);
    prep_kernel<<<(prep_threads + 255) / 256, 256>>>(w3, w4, w5, hw, f1w, f2w);
    {
        dim3 grid(LEN, B_USERS);
        hist_kernel<<<grid, 96>>>(tokens, emb);
    }
    conv_mma_kernel<<<B_USERS / 2, 512, conv_smem>>>(b3, b4, b5, hb);
    fc_kernel<<<B_USERS / TB, 256>>>(x, root, f1b, f2b, out);
}

// round 8
// speedup vs baseline: 4.8993x; 1.1807x over previous
#include <cuda_runtime.h>
#include <cuda_bf16.h>
#include <cstdint>

#define B_USERS 2048
#define P_POSTS 16384
#define LEN     50
#define D_EMB   300
#define NFILT   100
#define HID     64
#define INF_    768

#define DC16    19             // ceil(300/16) k-chunks of 16
#define WROWS   52             // 48 positions + max kk shift 4
#define WSTRIDE 156            // words per row; 156%32=28 -> ldmatrix conflict-free
#define USZ     (WROWS * WSTRIDE)   // 8112 words per user per (hi|lo)

// fragment counts (13 n8 tiles per group)
#define FRG0    (13 * 3 * DC16)     // 741
#define FRG1    (13 * 4 * DC16)     // 988
#define FRG2    (13 * 5 * DC16)     // 1235
#define NFRAG   (FRG0 + FRG1 + FRG2)  // 2964

// ---------------- scratch (device globals; no allocation) ----------------
__device__ int    g_segstart[B_USERS + 1];
__device__ float  g_hist[(size_t)B_USERS * LEN * D_EMB];   // [B, 50, 300]
__device__ float  g_rec[B_USERS * HID];
__device__ uint4  g_wf[NFRAG * 32];     // W frags: {hi_b0, hi_b1, lo_b0, lo_b1} per lane
__device__ float  g_hwt[300 * 64];      // hist_w transposed [j][o]
__device__ float  g_w1t[INF_ * 128];    // fc_w1 transposed [d][o]
__device__ float  g_w2t[128 * 64];      // fc_w2 transposed [d][j]

// ---------------- job table: 8 warps, cnt<=2, units 20/20/20/19/19/19/21/18 ----------------
struct Job { int8_t g, nb0, cnt; };
__constant__ Job c_slots[8][4] = {
    {{2, 0,2},{2, 2,2},{-1,0,0},{-1,0,0}},
    {{2, 4,2},{2, 6,2},{-1,0,0},{-1,0,0}},
    {{2, 8,2},{2,10,2},{-1,0,0},{-1,0,0}},
    {{2,12,1},{1, 0,2},{0, 0,2},{-1,0,0}},
    {{1, 2,2},{1, 4,2},{0, 2,1},{-1,0,0}},
    {{1, 6,2},{1, 8,2},{0, 3,1},{-1,0,0}},
    {{1,10,2},{1,12,1},{0, 4,2},{0, 6,1}},
    {{0, 7,2},{0, 9,2},{0,11,2},{-1,0,0}},
};

__device__ __forceinline__ uint32_t pack_bf16(float a, float b) {
    __nv_bfloat16 ha = __float2bfloat16_rn(a);
    __nv_bfloat16 hb = __float2bfloat16_rn(b);
    return ((uint32_t)__bfloat16_as_ushort(hb) << 16) | __bfloat16_as_ushort(ha);
}

#define MMA_BF16(c, a, b0, b1)                                                  \
    asm("mma.sync.aligned.m16n8k16.row.col.f32.bf16.bf16.f32 "                  \
        "{%0,%1,%2,%3},{%4,%5,%6,%7},{%8,%9},{%0,%1,%2,%3};"                    \
        : "+f"(c[0]), "+f"(c[1]), "+f"(c[2]), "+f"(c[3])                         \
        : "r"(a[0]), "r"(a[1]), "r"(a[2]), "r"(a[3]), "r"(b0), "r"(b1))

__device__ __forceinline__ void ldsm4(uint32_t* r, const uint32_t* p) {
    uint32_t addr = (uint32_t)__cvta_generic_to_shared(p);
    asm volatile("ldmatrix.sync.aligned.m8n8.x4.shared.b16 {%0,%1,%2,%3}, [%4];"
                 : "=r"(r[0]), "=r"(r[1]), "=r"(r[2]), "=r"(r[3]) : "r"(addr));
}

// ---------------- kernel A: segment offsets ----------------
__global__ void seg_bounds_kernel(const int* __restrict__ seg_ids) {
    int b = blockIdx.x * blockDim.x + threadIdx.x;
    if (b > B_USERS) return;
    int lo = 0, hi = P_POSTS;
    while (lo < hi) {
        int mid = (lo + hi) >> 1;
        if (seg_ids[mid] < b) lo = mid + 1; else hi = mid;
    }
    g_segstart[b] = lo;
}

// ---------------- prep: bf16 hi/lo W fragments + small transposes ----------------
__global__ void prep_kernel(const float* __restrict__ w3, const float* __restrict__ w4,
                            const float* __restrict__ w5, const float* __restrict__ hw_,
                            const float* __restrict__ w1, const float* __restrict__ w2) {
    int idx = blockIdx.x * 256 + threadIdx.x;
    if (idx < NFRAG * 32) {
        int lane = idx & 31;
        int frag = idx >> 5;
        int Kg; const float* w; int rel;
        if (frag < FRG0)               { Kg = 3; w = w3; rel = frag; }
        else if (frag < FRG0 + FRG1)   { Kg = 4; w = w4; rel = frag - FRG0; }
        else                           { Kg = 5; w = w5; rel = frag - FRG0 - FRG1; }
        int nb = rel / (Kg * DC16);
        int r2 = rel - nb * (Kg * DC16);
        int kk = r2 / DC16;
        int dc = r2 - kk * DC16;
        int n  = lane >> 2;
        int t  = lane & 3;
        int f  = nb * 8 + n;
        float v[4] = {0.f, 0.f, 0.f, 0.f};
        int dk[4] = {2*t, 2*t+1, 2*t+8, 2*t+9};
        if (f < NFILT) {
#pragma unroll
            for (int e = 0; e < 4; ++e) {
                int d = dc * 16 + dk[e];
                if (d < D_EMB) v[e] = __ldg(w + (f * D_EMB + d) * Kg + kk);
            }
        }
        float h[4], l[4];
#pragma unroll
        for (int e = 0; e < 4; ++e) {
            __nv_bfloat16 hb = __float2bfloat16_rn(v[e]);
            h[e] = __bfloat162float(hb);
            l[e] = v[e] - h[e];
        }
        uint4 out;
        out.x = pack_bf16(h[0], h[1]);
        out.y = pack_bf16(h[2], h[3]);
        out.z = pack_bf16(l[0], l[1]);
        out.w = pack_bf16(l[2], l[3]);
        g_wf[frag * 32 + lane] = out;
        return;
    }
    int i2 = idx - NFRAG * 32;                 // g_hwt: 300*64
    if (i2 >= 0 && i2 < 300 * 64) {
        int o = i2 & 63; int j = i2 >> 6;
        g_hwt[i2] = __ldg(hw_ + o * 300 + j);
        return;
    }
    int i3 = i2 - 300 * 64;                    // g_w1t: 768*128
    if (i3 >= 0 && i3 < INF_ * 128) {
        int o = i3 & 127; int d = i3 >> 7;
        g_w1t[i3] = __ldg(w1 + o * INF_ + d);
        return;
    }
    int i4 = i3 - INF_ * 128;                  // g_w2t: 128*64
    if (i4 >= 0 && i4 < 128 * 64) {
        int j = i4 & 63; int d = i4 >> 6;
        g_w2t[i4] = __ldg(w2 + j * 128 + d);
    }
}

// ---------------- kernel B: segment-mean of embeddings (float4) ----------------
__global__ void __launch_bounds__(96)
hist_kernel(const int* __restrict__ tokens, const float* __restrict__ emb) {
    int l = blockIdx.x;
    int b = blockIdx.y;
    int t = threadIdx.x;
    if (t >= 75) return;                     // 75 float4 = 300 floats
    int s = g_segstart[b], e = g_segstart[b + 1];

    float4 a = {0.f, 0.f, 0.f, 0.f};
    float4 c = {0.f, 0.f, 0.f, 0.f};
    int p = s;
    for (; p + 1 < e; p += 2) {
        int t0 = __ldg(tokens + p * LEN + l);
        int t1 = __ldg(tokens + (p + 1) * LEN + l);
        float4 v0 = __ldg((const float4*)(emb + (size_t)t0 * D_EMB) + t);
        float4 v1 = __ldg((const float4*)(emb + (size_t)t1 * D_EMB) + t);
        a.x += v0.x; a.y += v0.y; a.z += v0.z; a.w += v0.w;
        c.x += v1.x; c.y += v1.y; c.z += v1.z; c.w += v1.w;
    }
    if (p < e) {
        int t0 = __ldg(tokens + p * LEN + l);
        float4 v0 = __ldg((const float4*)(emb + (size_t)t0 * D_EMB) + t);
        a.x += v0.x; a.y += v0.y; a.z += v0.z; a.w += v0.w;
    }
    float sc = 1.0f / (float)max(e - s, 1);
    float4 o;
    o.x = (a.x + c.x) * sc; o.y = (a.y + c.y) * sc;
    o.z = (a.z + c.z) * sc; o.w = (a.w + c.w) * sc;
    ((float4*)(g_hist + ((size_t)b * LEN + l) * D_EMB))[t] = o;
}

// ---------------- conv job: prefetched weights + ldmatrix + pass-major bf16x3 ----------------
template <int CNT>
__device__ __forceinline__ void conv_job(const uint32_t* __restrict__ shi,
                                         const uint32_t* __restrict__ slo,
                                         int Kg, int gbase, int nb0, int Tg,
                                         const float* __restrict__ bp,
                                         float* __restrict__ sf) {
    int lane = threadIdx.x & 31;
    int g8   = lane >> 2;
    int t    = lane & 3;
    int lr     = lane & 7;
    int sel    = lane >> 3;
    int rowsel = lr + ((sel & 1) << 3);
    int colsel = (sel & 2) << 1;

    float acc[3][CNT][4];
#pragma unroll
    for (int mt = 0; mt < 3; ++mt)
#pragma unroll
        for (int j = 0; j < CNT; ++j)
#pragma unroll
            for (int c = 0; c < 4; ++c) acc[mt][j][c] = 0.f;

    for (int kk = 0; kk < Kg; ++kk) {
        const uint4* fptr = g_wf + (size_t)(gbase + (nb0 * Kg + kk) * DC16) * 32 + lane;
        const size_t jstride = (size_t)(Kg * DC16) * 32;
        int rbase = kk + rowsel;
        uint4 wv[CNT];
#pragma unroll
        for (int j = 0; j < CNT; ++j) wv[j] = __ldg(fptr + j * jstride);

        for (int dc = 0; dc < DC16; ++dc) {
            uint4 wn[CNT];
            if (dc + 1 < DC16) {
#pragma unroll
                for (int j = 0; j < CNT; ++j)
                    wn[j] = __ldg(fptr + j * jstride + (dc + 1) * 32);
            }
            uint32_t ah[3][4], al[3][4];
            int widx = dc * 8 + colsel;
#pragma unroll
            for (int mt = 0; mt < 3; ++mt) {
                const uint32_t* pa = shi + (mt * 16 + rbase) * WSTRIDE + widx;
                const uint32_t* pl = slo + (mt * 16 + rbase) * WSTRIDE + widx;
                ldsm4(ah[mt], pa);
                ldsm4(al[mt], pl);
            }
#pragma unroll
            for (int j = 0; j < CNT; ++j)
#pragma unroll
                for (int mt = 0; mt < 3; ++mt)
                    MMA_BF16(acc[mt][j], ah[mt], wv[j].x, wv[j].y);   // hi*hi
#pragma unroll
            for (int j = 0; j < CNT; ++j)
#pragma unroll
                for (int mt = 0; mt < 3; ++mt)
                    MMA_BF16(acc[mt][j], ah[mt], wv[j].z, wv[j].w);   // hi*lo
#pragma unroll
            for (int j = 0; j < CNT; ++j)
#pragma unroll
                for (int mt = 0; mt < 3; ++mt)
                    MMA_BF16(acc[mt][j], al[mt], wv[j].x, wv[j].y);   // lo*hi
#pragma unroll
            for (int j = 0; j < CNT; ++j) wv[j] = wn[j];
        }
    }

#pragma unroll
    for (int j = 0; j < CNT; ++j) {
        float m0 = -1e30f, m1 = -1e30f;
#pragma unroll
        for (int mt = 0; mt < 3; ++mt) {
            int p0 = mt * 16 + g8;
            int p1 = p0 + 8;
            if (p0 < Tg) { m0 = fmaxf(m0, acc[mt][j][0]); m1 = fmaxf(m1, acc[mt][j][1]); }
            if (p1 < Tg) { m0 = fmaxf(m0, acc[mt][j][2]); m1 = fmaxf(m1, acc[mt][j][3]); }
        }
#pragma unroll
        for (int off = 4; off < 32; off <<= 1) {
            m0 = fmaxf(m0, __shfl_xor_sync(0xffffffff, m0, off));
            m1 = fmaxf(m1, __shfl_xor_sync(0xffffffff, m1, off));
        }
        if (g8 == 0) {
            int f0 = (nb0 + j) * 8 + 2 * t;
            if (f0 < NFILT)     sf[f0]     = fmaxf(m0 + __ldg(bp + f0), 0.f);
            if (f0 + 1 < NFILT) sf[f0 + 1] = fmaxf(m1 + __ldg(bp + f0 + 1), 0.f);
        }
    }
}

__device__ __forceinline__ void run_job(const uint32_t* shi, const uint32_t* slo,
                                        int g, int nb0, int cnt,
                                        const float* b3, const float* b4,
                                        const float* b5, float* feats_u) {
    int Kg = 3 + g;
    int gbase = (g == 0) ? 0 : ((g == 1) ? FRG0 : (FRG0 + FRG1));
    int Tg = 51 - Kg;
    const float* bp = (g == 0) ? b3 : ((g == 1) ? b4 : b5);
    float* sf = feats_u + g * 100;
    if (cnt == 2) conv_job<2>(shi, slo, Kg, gbase, nb0, Tg, bp, sf);
    else          conv_job<1>(shi, slo, Kg, gbase, nb0, Tg, bp, sf);
}

// ---------------- kernel C: TextCNN via bf16x3 tensor cores, 1 user / 256 thr ----------------
__global__ void __launch_bounds__(256, 3)
conv_mma_kernel(const float* __restrict__ b3, const float* __restrict__ b4,
                const float* __restrict__ b5, const float* __restrict__ hb_) {
    extern __shared__ uint32_t shw[];           // [hi USZ][lo USZ][feats 304]
    float* feats = (float*)(shw + 2 * USZ);
    int tid = threadIdx.x;
    int b   = blockIdx.x;

    // load user's hist, split into bf16 hi/lo, pack pairs
    for (int idx = tid; idx < USZ; idx += 256) {
        int r   = idx / WSTRIDE;
        int w   = idx - r * WSTRIDE;
        int col = w * 2;
        float x0 = 0.f, x1 = 0.f;
        if (r < LEN && col < D_EMB) {
            const float* src = g_hist + (((size_t)b) * LEN + r) * D_EMB;
            x0 = src[col];
            if (col + 1 < D_EMB) x1 = src[col + 1];
        }
        __nv_bfloat16 h0 = __float2bfloat16_rn(x0);
        __nv_bfloat16 h1 = __float2bfloat16_rn(x1);
        float l0f = x0 - __bfloat162float(h0);
        float l1f = x1 - __bfloat162float(h1);
        shw[idx]       = ((uint32_t)__bfloat16_as_ushort(h1) << 16) |
                         __bfloat16_as_ushort(h0);
        shw[USZ + idx] = pack_bf16(l0f, l1f);
    }
    __syncthreads();

    int slot = tid >> 5;
    const uint32_t* shi = shw;
    const uint32_t* slo = shw + USZ;

#pragma unroll
    for (int q = 0; q < 4; ++q) {
        Job jb = c_slots[slot][q];
        if (jb.g < 0) continue;
        run_job(shi, slo, jb.g, jb.nb0, jb.cnt, b3, b4, b5, feats);
    }
    __syncthreads();

    // rec GEMM: [300 feats] x [64 outs]
    if (tid < 64) {
        int o = tid;
        float r = __ldg(hb_ + o);
#pragma unroll 4
        for (int j = 0; j < 300; ++j)
            r = fmaf(feats[j], __ldg(g_hwt + j * HID + o), r);
        g_rec[b * HID + o] = r;
    }
}

// ---------------- kernel D: fc_out on root features + final add ----------------
#define TB 8
__global__ void __launch_bounds__(256)
fc_kernel(const float* __restrict__ x, const int* __restrict__ root,
          const float* __restrict__ b1, const float* __restrict__ b2,
          float* __restrict__ out) {
    __shared__ float sx[TB * INF_];
    __shared__ float hh[TB * 128];
    __shared__ int   ridx[TB];
    int tid = threadIdx.x;
    int b0 = blockIdx.x * TB;

    if (tid < TB) ridx[tid] = __ldg(root + b0 + tid);
    __syncthreads();
    for (int i = tid; i < TB * INF_; i += 256) {
        int u = i / INF_; int d = i - u * INF_;
        sx[i] = __ldg(x + (size_t)ridx[u] * INF_ + d);
    }
    __syncthreads();

    {
        int o  = tid & 127;
        int ug = tid >> 7;
        float acc[4] = {0.f, 0.f, 0.f, 0.f};
        for (int d = 0; d < INF_; ++d) {
            float wv = __ldg(g_w1t + d * 128 + o);
#pragma unroll
            for (int uu = 0; uu < 4; ++uu)
                acc[uu] = fmaf(sx[(ug * 4 + uu) * INF_ + d], wv, acc[uu]);
        }
        float bb = __ldg(b1 + o);
#pragma unroll
        for (int uu = 0; uu < 4; ++uu)
            hh[(ug * 4 + uu) * 128 + o] = fmaxf(acc[uu] + bb, 0.f);
    }
    __syncthreads();

    {
        int j = tid & 63;
        int q = tid >> 6;
        int u0 = 2 * q, u1 = 2 * q + 1;
        float a0 = 0.f, a1 = 0.f;
        for (int d = 0; d < 128; ++d) {
            float wv = __ldg(g_w2t + d * 64 + j);
            a0 = fmaf(hh[u0 * 128 + d], wv, a0);
            a1 = fmaf(hh[u1 * 128 + d], wv, a1);
        }
        float bb = __ldg(b2 + j);
        out[(b0 + u0) * HID + j] = a0 + bb + g_rec[(b0 + u0) * HID + j];
        out[(b0 + u1) * HID + j] = a1 + bb + g_rec[(b0 + u1) * HID + j];
    }
}

// ---------------- launch ----------------
extern "C" void kernel_launch(void* const* d_in, const int* in_sizes, int n_in,
                              void* d_out, int out_size) {
    const float* x        = (const float*)d_in[0];
    const int*   root     = (const int*)  d_in[1];
    const int*   tokens   = (const int*)  d_in[2];
    const int*   seg_ids  = (const int*)  d_in[3];
    const float* emb      = (const float*)d_in[4];
    const float* w3 = (const float*)d_in[5];   const float* b3 = (const float*)d_in[6];
    const float* w4 = (const float*)d_in[7];   const float* b4 = (const float*)d_in[8];
    const float* w5 = (const float*)d_in[9];   const float* b5 = (const float*)d_in[10];
    const float* hw = (const float*)d_in[11];  const float* hb = (const float*)d_in[12];
    const float* f1w = (const float*)d_in[13]; const float* f1b = (const float*)d_in[14];
    const float* f2w = (const float*)d_in[15]; const float* f2b = (const float*)d_in[16];
    float* out = (float*)d_out;

    const int conv_smem = (2 * USZ + 304) * (int)sizeof(uint32_t);  // ~66.1 KB
    cudaFuncSetAttribute(conv_mma_kernel, cudaFuncAttributeMaxDynamicSharedMemorySize,
                         conv_smem);

    int prep_threads = NFRAG * 32 + 300 * 64 + INF_ * 128 + 128 * 64;
    seg_bounds_kernel<<<(B_USERS + 1 + 255) / 256, 256>>>(seg_ids);
    prep_kernel<<<(prep_threads + 255) / 256, 256>>>(w3, w4, w5, hw, f1w, f2w);
    {
        dim3 grid(LEN, B_USERS);
        hist_kernel<<<grid, 96>>>(tokens, emb);
    }
    conv_mma_kernel<<<B_USERS, 256, conv_smem>>>(b3, b4, b5, hb);
    fc_kernel<<<B_USERS / TB, 256>>>(x, root, f1b, f2b, out);
}

// round 9
// speedup vs baseline: 5.0335x; 1.0274x over previous
#include <cuda_runtime.h>
#include <cuda_bf16.h>
#include <cstdint>

#define B_USERS 2048
#define P_POSTS 16384
#define LEN     50
#define D_EMB   300
#define NFILT   100
#define HID     64
#define INF_    768

#define DC16    19             // ceil(300/16) k-chunks of 16
#define WROWS   52             // 48 positions + max kk shift 4
#define WSTRIDE 156            // words per row; 156%32=28 -> ldmatrix conflict-free
#define USZ     (WROWS * WSTRIDE)   // 8112 words per user per (hi|lo)

// fragment counts (13 n8 tiles per group)
#define FRG0    (13 * 3 * DC16)     // 741
#define FRG1    (13 * 4 * DC16)     // 988
#define FRG2    (13 * 5 * DC16)     // 1235
#define NFRAG   (FRG0 + FRG1 + FRG2)  // 2964

// ---------------- scratch (device globals; no allocation) ----------------
__device__ int    g_segstart[B_USERS + 1];
__device__ uint4  g_hhi[(size_t)B_USERS * USZ / 4];   // packed bf16 hi, conv layout
__device__ uint4  g_hlo[(size_t)B_USERS * USZ / 4];   // packed bf16 lo
__device__ float  g_rec[B_USERS * HID];
__device__ uint4  g_wf[NFRAG * 32];     // W frags: {hi_b0, hi_b1, lo_b0, lo_b1} per lane
__device__ float  g_hwt[300 * 64];      // hist_w transposed [j][o]
__device__ float  g_w1t[INF_ * 128];    // fc_w1 transposed [d][o]
__device__ float  g_w2t[128 * 64];      // fc_w2 transposed [d][j]

// ---------------- job table: 8 warps, cnt<=2 ----------------
struct Job { int8_t g, nb0, cnt; };
__constant__ Job c_slots[8][4] = {
    {{2, 0,2},{2, 2,2},{-1,0,0},{-1,0,0}},
    {{2, 4,2},{2, 6,2},{-1,0,0},{-1,0,0}},
    {{2, 8,2},{2,10,2},{-1,0,0},{-1,0,0}},
    {{2,12,1},{1, 0,2},{0, 0,2},{-1,0,0}},
    {{1, 2,2},{1, 4,2},{0, 2,1},{-1,0,0}},
    {{1, 6,2},{1, 8,2},{0, 3,1},{-1,0,0}},
    {{1,10,2},{1,12,1},{0, 4,2},{0, 6,1}},
    {{0, 7,2},{0, 9,2},{0,11,2},{-1,0,0}},
};

__device__ __forceinline__ uint32_t pack_bf16(float a, float b) {
    __nv_bfloat16 ha = __float2bfloat16_rn(a);
    __nv_bfloat16 hb = __float2bfloat16_rn(b);
    return ((uint32_t)__bfloat16_as_ushort(hb) << 16) | __bfloat16_as_ushort(ha);
}

#define MMA_BF16(c, a, b0, b1)                                                  \
    asm("mma.sync.aligned.m16n8k16.row.col.f32.bf16.bf16.f32 "                  \
        "{%0,%1,%2,%3},{%4,%5,%6,%7},{%8,%9},{%0,%1,%2,%3};"                    \
        : "+f"(c[0]), "+f"(c[1]), "+f"(c[2]), "+f"(c[3])                         \
        : "r"(a[0]), "r"(a[1]), "r"(a[2]), "r"(a[3]), "r"(b0), "r"(b1))

__device__ __forceinline__ void ldsm4(uint32_t* r, const uint32_t* p) {
    uint32_t addr = (uint32_t)__cvta_generic_to_shared(p);
    asm volatile("ldmatrix.sync.aligned.m8n8.x4.shared.b16 {%0,%1,%2,%3}, [%4];"
                 : "=r"(r[0]), "=r"(r[1]), "=r"(r[2]), "=r"(r[3]) : "r"(addr));
}

// ---------------- kernel A: segment offsets ----------------
__global__ void seg_bounds_kernel(const int* __restrict__ seg_ids) {
    int b = blockIdx.x * blockDim.x + threadIdx.x;
    if (b > B_USERS) return;
    int lo = 0, hi = P_POSTS;
    while (lo < hi) {
        int mid = (lo + hi) >> 1;
        if (seg_ids[mid] < b) lo = mid + 1; else hi = mid;
    }
    g_segstart[b] = lo;
}

// ---------------- prep: bf16 hi/lo W fragments + small transposes ----------------
__global__ void prep_kernel(const float* __restrict__ w3, const float* __restrict__ w4,
                            const float* __restrict__ w5, const float* __restrict__ hw_,
                            const float* __restrict__ w1, const float* __restrict__ w2) {
    int idx = blockIdx.x * 256 + threadIdx.x;
    if (idx < NFRAG * 32) {
        int lane = idx & 31;
        int frag = idx >> 5;
        int Kg; const float* w; int rel;
        if (frag < FRG0)               { Kg = 3; w = w3; rel = frag; }
        else if (frag < FRG0 + FRG1)   { Kg = 4; w = w4; rel = frag - FRG0; }
        else                           { Kg = 5; w = w5; rel = frag - FRG0 - FRG1; }
        int nb = rel / (Kg * DC16);
        int r2 = rel - nb * (Kg * DC16);
        int kk = r2 / DC16;
        int dc = r2 - kk * DC16;
        int n  = lane >> 2;
        int t  = lane & 3;
        int f  = nb * 8 + n;
        float v[4] = {0.f, 0.f, 0.f, 0.f};
        int dk[4] = {2*t, 2*t+1, 2*t+8, 2*t+9};
        if (f < NFILT) {
#pragma unroll
            for (int e = 0; e < 4; ++e) {
                int d = dc * 16 + dk[e];
                if (d < D_EMB) v[e] = __ldg(w + (f * D_EMB + d) * Kg + kk);
            }
        }
        float h[4], l[4];
#pragma unroll
        for (int e = 0; e < 4; ++e) {
            __nv_bfloat16 hb = __float2bfloat16_rn(v[e]);
            h[e] = __bfloat162float(hb);
            l[e] = v[e] - h[e];
        }
        uint4 out;
        out.x = pack_bf16(h[0], h[1]);
        out.y = pack_bf16(h[2], h[3]);
        out.z = pack_bf16(l[0], l[1]);
        out.w = pack_bf16(l[2], l[3]);
        g_wf[frag * 32 + lane] = out;
        return;
    }
    int i2 = idx - NFRAG * 32;                 // g_hwt: 300*64
    if (i2 >= 0 && i2 < 300 * 64) {
        int o = i2 & 63; int j = i2 >> 6;
        g_hwt[i2] = __ldg(hw_ + o * 300 + j);
        return;
    }
    int i3 = i2 - 300 * 64;                    // g_w1t: 768*128
    if (i3 >= 0 && i3 < INF_ * 128) {
        int o = i3 & 127; int d = i3 >> 7;
        g_w1t[i3] = __ldg(w1 + o * INF_ + d);
        return;
    }
    int i4 = i3 - INF_ * 128;                  // g_w2t: 128*64
    if (i4 >= 0 && i4 < 128 * 64) {
        int j = i4 & 63; int d = i4 >> 6;
        g_w2t[i4] = __ldg(w2 + j * 128 + d);
    }
}

// ---------------- kernel B: segment-mean -> packed bf16 hi/lo, conv layout ----------------
// grid = (52, B_USERS): rows 50,51 are pad (zeroed). 96 threads; t<75 compute.
__global__ void __launch_bounds__(96)
hist_kernel(const int* __restrict__ tokens, const float* __restrict__ emb) {
    int l = blockIdx.x;
    int b = blockIdx.y;
    int t = threadIdx.x;
    uint2* hhi = (uint2*)g_hhi;
    uint2* hlo = (uint2*)g_hlo;
    size_t rowbase = ((size_t)b * USZ + l * WSTRIDE) >> 1;   // uint2 index

    if (l >= LEN) {                            // pad rows: zero all 156 words
        if (t < WSTRIDE / 2) {
            hhi[rowbase + t] = make_uint2(0u, 0u);
            hlo[rowbase + t] = make_uint2(0u, 0u);
        }
        return;
    }
    if (t >= 75) {                             // pad words 150..155
        if (t < 78) {
            hhi[rowbase + t] = make_uint2(0u, 0u);
            hlo[rowbase + t] = make_uint2(0u, 0u);
        }
        return;
    }

    int s = g_segstart[b], e = g_segstart[b + 1];
    float4 a = {0.f, 0.f, 0.f, 0.f};
    float4 c = {0.f, 0.f, 0.f, 0.f};
    int p = s;
    for (; p + 3 < e; p += 4) {
        int t0 = __ldg(tokens + p * LEN + l);
        int t1 = __ldg(tokens + (p + 1) * LEN + l);
        int t2 = __ldg(tokens + (p + 2) * LEN + l);
        int t3 = __ldg(tokens + (p + 3) * LEN + l);
        float4 v0 = __ldg((const float4*)(emb + (size_t)t0 * D_EMB) + t);
        float4 v1 = __ldg((const float4*)(emb + (size_t)t1 * D_EMB) + t);
        float4 v2 = __ldg((const float4*)(emb + (size_t)t2 * D_EMB) + t);
        float4 v3 = __ldg((const float4*)(emb + (size_t)t3 * D_EMB) + t);
        a.x += v0.x + v2.x; a.y += v0.y + v2.y; a.z += v0.z + v2.z; a.w += v0.w + v2.w;
        c.x += v1.x + v3.x; c.y += v1.y + v3.y; c.z += v1.z + v3.z; c.w += v1.w + v3.w;
    }
    for (; p < e; ++p) {
        int t0 = __ldg(tokens + p * LEN + l);
        float4 v0 = __ldg((const float4*)(emb + (size_t)t0 * D_EMB) + t);
        a.x += v0.x; a.y += v0.y; a.z += v0.z; a.w += v0.w;
    }
    float sc = 1.0f / (float)max(e - s, 1);
    float x0 = (a.x + c.x) * sc, x1 = (a.y + c.y) * sc;
    float x2 = (a.z + c.z) * sc, x3 = (a.w + c.w) * sc;

    __nv_bfloat16 h0 = __float2bfloat16_rn(x0), h1 = __float2bfloat16_rn(x1);
    __nv_bfloat16 h2 = __float2bfloat16_rn(x2), h3 = __float2bfloat16_rn(x3);
    uint2 whi, wlo;
    whi.x = ((uint32_t)__bfloat16_as_ushort(h1) << 16) | __bfloat16_as_ushort(h0);
    whi.y = ((uint32_t)__bfloat16_as_ushort(h3) << 16) | __bfloat16_as_ushort(h2);
    wlo.x = pack_bf16(x0 - __bfloat162float(h0), x1 - __bfloat162float(h1));
    wlo.y = pack_bf16(x2 - __bfloat162float(h2), x3 - __bfloat162float(h3));
    hhi[rowbase + t] = whi;
    hlo[rowbase + t] = wlo;
}

// ---------------- conv job: prefetched weights + ldmatrix + pass-major bf16x3 ----------------
template <int CNT>
__device__ __forceinline__ void conv_job(const uint32_t* __restrict__ shi,
                                         const uint32_t* __restrict__ slo,
                                         int Kg, int gbase, int nb0, int Tg,
                                         const float* __restrict__ bp,
                                         float* __restrict__ sf) {
    int lane = threadIdx.x & 31;
    int g8   = lane >> 2;
    int t    = lane & 3;
    int lr     = lane & 7;
    int sel    = lane >> 3;
    int rowsel = lr + ((sel & 1) << 3);
    int colsel = (sel & 2) << 1;

    float acc[3][CNT][4];
#pragma unroll
    for (int mt = 0; mt < 3; ++mt)
#pragma unroll
        for (int j = 0; j < CNT; ++j)
#pragma unroll
            for (int c = 0; c < 4; ++c) acc[mt][j][c] = 0.f;

    for (int kk = 0; kk < Kg; ++kk) {
        const uint4* fptr = g_wf + (size_t)(gbase + (nb0 * Kg + kk) * DC16) * 32 + lane;
        const size_t jstride = (size_t)(Kg * DC16) * 32;
        int rbase = kk + rowsel;
        uint4 wv[CNT];
#pragma unroll
        for (int j = 0; j < CNT; ++j) wv[j] = __ldg(fptr + j * jstride);

        for (int dc = 0; dc < DC16; ++dc) {
            uint4 wn[CNT];
            if (dc + 1 < DC16) {
#pragma unroll
                for (int j = 0; j < CNT; ++j)
                    wn[j] = __ldg(fptr + j * jstride + (dc + 1) * 32);
            }
            uint32_t ah[3][4], al[3][4];
            int widx = dc * 8 + colsel;
#pragma unroll
            for (int mt = 0; mt < 3; ++mt) {
                const uint32_t* pa = shi + (mt * 16 + rbase) * WSTRIDE + widx;
                const uint32_t* pl = slo + (mt * 16 + rbase) * WSTRIDE + widx;
                ldsm4(ah[mt], pa);
                ldsm4(al[mt], pl);
            }
#pragma unroll
            for (int j = 0; j < CNT; ++j)
#pragma unroll
                for (int mt = 0; mt < 3; ++mt)
                    MMA_BF16(acc[mt][j], ah[mt], wv[j].x, wv[j].y);   // hi*hi
#pragma unroll
            for (int j = 0; j < CNT; ++j)
#pragma unroll
                for (int mt = 0; mt < 3; ++mt)
                    MMA_BF16(acc[mt][j], ah[mt], wv[j].z, wv[j].w);   // hi*lo
#pragma unroll
            for (int j = 0; j < CNT; ++j)
#pragma unroll
                for (int mt = 0; mt < 3; ++mt)
                    MMA_BF16(acc[mt][j], al[mt], wv[j].x, wv[j].y);   // lo*hi
#pragma unroll
            for (int j = 0; j < CNT; ++j) wv[j] = wn[j];
        }
    }

#pragma unroll
    for (int j = 0; j < CNT; ++j) {
        float m0 = -1e30f, m1 = -1e30f;
#pragma unroll
        for (int mt = 0; mt < 3; ++mt) {
            int p0 = mt * 16 + g8;
            int p1 = p0 + 8;
            if (p0 < Tg) { m0 = fmaxf(m0, acc[mt][j][0]); m1 = fmaxf(m1, acc[mt][j][1]); }
            if (p1 < Tg) { m0 = fmaxf(m0, acc[mt][j][2]); m1 = fmaxf(m1, acc[mt][j][3]); }
        }
#pragma unroll
        for (int off = 4; off < 32; off <<= 1) {
            m0 = fmaxf(m0, __shfl_xor_sync(0xffffffff, m0, off));
            m1 = fmaxf(m1, __shfl_xor_sync(0xffffffff, m1, off));
        }
        if (g8 == 0) {
            int f0 = (nb0 + j) * 8 + 2 * t;
            if (f0 < NFILT)     sf[f0]     = fmaxf(m0 + __ldg(bp + f0), 0.f);
            if (f0 + 1 < NFILT) sf[f0 + 1] = fmaxf(m1 + __ldg(bp + f0 + 1), 0.f);
        }
    }
}

__device__ __forceinline__ void run_job(const uint32_t* shi, const uint32_t* slo,
                                        int g, int nb0, int cnt,
                                        const float* b3, const float* b4,
                                        const float* b5, float* feats_u) {
    int Kg = 3 + g;
    int gbase = (g == 0) ? 0 : ((g == 1) ? FRG0 : (FRG0 + FRG1));
    int Tg = 51 - Kg;
    const float* bp = (g == 0) ? b3 : ((g == 1) ? b4 : b5);
    float* sf = feats_u + g * 100;
    if (cnt == 2) conv_job<2>(shi, slo, Kg, gbase, nb0, Tg, bp, sf);
    else          conv_job<1>(shi, slo, Kg, gbase, nb0, Tg, bp, sf);
}

// ---------------- kernel C: TextCNN via bf16x3 tensor cores, 1 user / 256 thr ----------------
__global__ void __launch_bounds__(256, 3)
conv_mma_kernel(const float* __restrict__ b3, const float* __restrict__ b4,
                const float* __restrict__ b5, const float* __restrict__ hb_) {
    extern __shared__ uint32_t shw[];           // [hi USZ][lo USZ][feats 304]
    float* feats = (float*)(shw + 2 * USZ);
    int tid = threadIdx.x;
    int b   = blockIdx.x;

    // straight copy: hist already packed in conv layout
    {
        uint4* dhi = (uint4*)shw;
        uint4* dlo = (uint4*)(shw + USZ);
        const uint4* shi4 = g_hhi + (size_t)b * (USZ / 4);
        const uint4* slo4 = g_hlo + (size_t)b * (USZ / 4);
        for (int i = tid; i < USZ / 4; i += 256) {
            dhi[i] = __ldg(shi4 + i);
            dlo[i] = __ldg(slo4 + i);
        }
    }
    __syncthreads();

    int slot = tid >> 5;
    const uint32_t* shi = shw;
    const uint32_t* slo = shw + USZ;

#pragma unroll
    for (int q = 0; q < 4; ++q) {
        Job jb = c_slots[slot][q];
        if (jb.g < 0) continue;
        run_job(shi, slo, jb.g, jb.nb0, jb.cnt, b3, b4, b5, feats);
    }
    __syncthreads();

    // rec GEMM: [300 feats] x [64 outs]
    if (tid < 64) {
        int o = tid;
        float r = __ldg(hb_ + o);
#pragma unroll 4
        for (int j = 0; j < 300; ++j)
            r = fmaf(feats[j], __ldg(g_hwt + j * HID + o), r);
        g_rec[b * HID + o] = r;
    }
}

// ---------------- kernel D: fc_out on root features + final add ----------------
#define TB 8
__global__ void __launch_bounds__(256)
fc_kernel(const float* __restrict__ x, const int* __restrict__ root,
          const float* __restrict__ b1, const float* __restrict__ b2,
          float* __restrict__ out) {
    __shared__ float sx[TB * INF_];
    __shared__ float hh[TB * 128];
    __shared__ int   ridx[TB];
    int tid = threadIdx.x;
    int b0 = blockIdx.x * TB;

    if (tid < TB) ridx[tid] = __ldg(root + b0 + tid);
    __syncthreads();
    for (int i = tid; i < TB * INF_; i += 256) {
        int u = i / INF_; int d = i - u * INF_;
        sx[i] = __ldg(x + (size_t)ridx[u] * INF_ + d);
    }
    __syncthreads();

    {
        int o  = tid & 127;
        int ug = tid >> 7;
        float acc[4] = {0.f, 0.f, 0.f, 0.f};
        for (int d = 0; d < INF_; ++d) {
            float wv = __ldg(g_w1t + d * 128 + o);
#pragma unroll
            for (int uu = 0; uu < 4; ++uu)
                acc[uu] = fmaf(sx[(ug * 4 + uu) * INF_ + d], wv, acc[uu]);
        }
        float bb = __ldg(b1 + o);
#pragma unroll
        for (int uu = 0; uu < 4; ++uu)
            hh[(ug * 4 + uu) * 128 + o] = fmaxf(acc[uu] + bb, 0.f);
    }
    __syncthreads();

    {
        int j = tid & 63;
        int q = tid >> 6;
        int u0 = 2 * q, u1 = 2 * q + 1;
        float a0 = 0.f, a1 = 0.f;
        for (int d = 0; d < 128; ++d) {
            float wv = __ldg(g_w2t + d * 64 + j);
            a0 = fmaf(hh[u0 * 128 + d], wv, a0);
            a1 = fmaf(hh[u1 * 128 + d], wv, a1);
        }
        float bb = __ldg(b2 + j);
        out[(b0 + u0) * HID + j] = a0 + bb + g_rec[(b0 + u0) * HID + j];
        out[(b0 + u1) * HID + j] = a1 + bb + g_rec[(b0 + u1) * HID + j];
    }
}

// ---------------- launch ----------------
extern "C" void kernel_launch(void* const* d_in, const int* in_sizes, int n_in,
                              void* d_out, int out_size) {
    const float* x        = (const float*)d_in[0];
    const int*   root     = (const int*)  d_in[1];
    const int*   tokens   = (const int*)  d_in[2];
    const int*   seg_ids  = (const int*)  d_in[3];
    const float* emb      = (const float*)d_in[4];
    const float* w3 = (const float*)d_in[5];   const float* b3 = (const float*)d_in[6];
    const float* w4 = (const float*)d_in[7];   const float* b4 = (const float*)d_in[8];
    const float* w5 = (const float*)d_in[9];   const float* b5 = (const float*)d_in[10];
    const float* hw = (const float*)d_in[11];  const float* hb = (const float*)d_in[12];
    const float* f1w = (const float*)d_in[13]; const float* f1b = (const float*)d_in[14];
    const float* f2w = (const float*)d_in[15]; const float* f2b = (const float*)d_in[16];
    float* out = (float*)d_out;

    const int conv_smem = (2 * USZ + 304) * (int)sizeof(uint32_t);  // ~66.1 KB
    cudaFuncSetAttribute(conv_mma_kernel, cudaFuncAttributeMaxDynamicSharedMemorySize,
                         conv_smem);

    int prep_threads = NFRAG * 32 + 300 * 64 + INF_ * 128 + 128 * 64;
    seg_bounds_kernel<<<(B_USERS + 1 + 255) / 256, 256>>>(seg_ids);
    prep_kernel<<<(prep_threads + 255) / 256, 256>>>(w3, w4, w5, hw, f1w, f2w);
    {
        dim3 grid(WROWS, B_USERS);               // 52 rows: 50 data + 2 pad
        hist_kernel<<<grid, 96>>>(tokens, emb);
    }
    conv_mma_kernel<<<B_USERS, 256, conv_smem>>>(b3, b4, b5, hb);
    fc_kernel<<<B_USERS / TB, 256>>>(x, root, f1b, f2b, out);
}